// round 9
// baseline (speedup 1.0000x reference)
#include <cuda_runtime.h>
#include <cuda_bf16.h>
#include <cuda_fp16.h>
#include <cstdint>

// Problem constants
#define BB 512
#define TT 128
#define II 512
#define HH 512
#define CC 97
#define SS 26
#define G4H 2048           // 4*H
#define NCOMB 2560         // H + 4H
#define WIH_LD 609         // I + C

// Interleaved gate index: m = 4*u + g  <->  original row g*512 + u

// ---------------- device scratch (static, no allocs) ----------------
__device__ __half2 g_feat_h[(size_t)BB * TT * HH / 2];   // 64 MB fp16 feat
__device__ __half2 g_H_h[(size_t)BB * TT * II / 2];      // 64 MB fp16 batch_H
__device__ __half  g_h_h[BB * HH];                       // fp16 hidden state
__device__ float   g_c[BB * HH];
__device__ float   g_Y[BB * NCOMB];                      // [hp | h@Whh_il^T] fp32
__device__ float   g_e[BB * TT];                         // attention energies
__device__ __half2 g_ctx_h[BB * II / 2];                 // fp16 context
__device__ __half  g_outh_h[(size_t)BB * SS * HH];       // fp16 step outputs
__device__ __half  g_Wx_h[G4H * II];                     // W_ih[:, :I], gate-interleaved
__device__ __half  g_Wcomb_h[NCOMB * HH];                // [W_hid ; W_hh interleaved]
__device__ __half  g_Wfeat_h[HH * II];
__device__ __half  g_Wgen_h[CC * HH];
__device__ float   g_bcomb[NCOMB];                       // [b_hid ; 0]
__device__ float   g_WohT[CC * G4H];                     // W_ih[:, I:]^T interleaved
__device__ float   g_bg[G4H];                            // (b_ih + b_hh) interleaved

// ---------------- pack / init kernel ----------------
__global__ void pack_kernel(const float* __restrict__ W_ih,
                            const float* __restrict__ b_ih,
                            const float* __restrict__ b_hh,
                            const float* __restrict__ W_hid,
                            const float* __restrict__ W_hh,
                            const float* __restrict__ b_hid,
                            const float* __restrict__ W_feat,
                            const float* __restrict__ W_gen,
                            const float* __restrict__ batch_H)
{
    const int stride = gridDim.x * blockDim.x;
    const int t0 = blockIdx.x * blockDim.x + threadIdx.x;
    for (int i = t0; i < G4H * II; i += stride) {
        int n = i >> 9, k = i & 511;
        int u = n >> 2, g = n & 3;
        g_Wx_h[i] = __float2half_rn(W_ih[(g * 512 + u) * WIH_LD + k]);
    }
    for (int i = t0; i < NCOMB * HH; i += stride) {
        int n = i >> 9, k = i & 511;
        float v;
        if (n < HH) v = W_hid[n * HH + k];
        else {
            int m = n - HH, u = m >> 2, g = m & 3;
            v = W_hh[(g * 512 + u) * HH + k];
        }
        g_Wcomb_h[i] = __float2half_rn(v);
    }
    for (int i = t0; i < HH * II; i += stride)
        g_Wfeat_h[i] = __float2half_rn(W_feat[i]);
    for (int i = t0; i < CC * HH; i += stride)
        g_Wgen_h[i] = __float2half_rn(W_gen[i]);
    for (int i = t0; i < CC * G4H; i += stride) {
        int cls = i >> 11, m = i & 2047;
        int u = m >> 2, g = m & 3;
        g_WohT[i] = W_ih[(g * 512 + u) * WIH_LD + II + cls];
    }
    for (int i = t0; i < G4H; i += stride) {
        int u = i >> 2, g = i & 3;
        g_bg[i] = b_ih[g * 512 + u] + b_hh[g * 512 + u];
    }
    for (int i = t0; i < NCOMB; i += stride) g_bcomb[i] = (i < HH) ? b_hid[i] : 0.f;
    for (int i = t0; i < BB * HH; i += stride) {
        g_h_h[i] = __float2half_rn(0.f);
        g_c[i] = 0.f;
    }
    const size_t nh2 = (size_t)BB * TT * II / 2;
    const float2* src = reinterpret_cast<const float2*>(batch_H);
    for (size_t i = t0; i < nh2; i += stride)
        g_H_h[i] = __float22half2_rn(src[i]);
}

#define MMA_F16(d, a, b)                                                         \
    asm volatile("mma.sync.aligned.m16n8k16.row.col.f32.f16.f16.f32 "            \
                 "{%0,%1,%2,%3}, {%4,%5,%6,%7}, {%8,%9}, {%0,%1,%2,%3};"         \
                 : "+f"(d[0]), "+f"(d[1]), "+f"(d[2]), "+f"(d[3])                \
                 : "r"(a[0]), "r"(a[1]), "r"(a[2]), "r"(a[3]),                   \
                   "r"(b[0]), "r"(b[1]))

#define SMP 56

// ---------------- split-K fp16 GEMM, 64x64 tile, 256 threads ----------------
// 8 warps: 2x2 warp tiles x 2 K-groups; smem reduction at the end.
__global__ __launch_bounds__(256)
void gemm_f16_sk(const __half* __restrict__ A, const __half* __restrict__ B,
                 const float* __restrict__ bias, float* __restrict__ C,
                 __half* __restrict__ Ch,
                 int M, int N, int K, int ldc)
{
    __shared__ __half As[2][64][SMP];
    __shared__ __half Bs[2][64][SMP];
    __shared__ float red[64][65];

    const int tid  = threadIdx.x;
    const int bm   = blockIdx.x * 64;
    const int bn   = blockIdx.y * 64;
    const int w    = tid >> 5, lane = tid & 31;
    const int g    = lane >> 2, tg = lane & 3;
    const int kg   = w >> 2;
    const int ws   = w & 3;
    const int wm   = (ws & 1) * 32;
    const int wn   = (ws >> 1) * 32;
    const int ks   = kg << 4;

    float acc[2][4][4];
#pragma unroll
    for (int mt = 0; mt < 2; ++mt)
#pragma unroll
        for (int nt = 0; nt < 4; ++nt)
#pragma unroll
            for (int r = 0; r < 4; ++r) acc[mt][nt][r] = 0.f;

    uint4 stA, stB;
    const uint4 z4 = make_uint4(0u, 0u, 0u, 0u);
    const int nk = K >> 5;
    const int kld = K >> 3;
    const int lr = tid >> 2, lc = tid & 3;

    auto ldg = [&](int k0) {
        const uint4* Ar = reinterpret_cast<const uint4*>(A) + (size_t)(bm + lr) * kld + (k0 >> 3) + lc;
        const uint4* Br = reinterpret_cast<const uint4*>(B) + (size_t)(bn + lr) * kld + (k0 >> 3) + lc;
        stA = (bm + lr < M) ? *Ar : z4;
        stB = (bn + lr < N) ? *Br : z4;
    };
    auto sts = [&](int buf) {
        *reinterpret_cast<uint4*>(&As[buf][lr][lc * 8]) = stA;
        *reinterpret_cast<uint4*>(&Bs[buf][lr][lc * 8]) = stB;
    };

    ldg(0); sts(0);
    __syncthreads();

    for (int kt = 0; kt < nk; ++kt) {
        const int buf = kt & 1;
        if (kt + 1 < nk) ldg((kt + 1) << 5);

        unsigned a[2][4];
#pragma unroll
        for (int mt = 0; mt < 2; ++mt) {
            int r0 = wm + mt * 16 + g;
            a[mt][0] = *reinterpret_cast<const unsigned*>(&As[buf][r0][ks + 2 * tg]);
            a[mt][1] = *reinterpret_cast<const unsigned*>(&As[buf][r0 + 8][ks + 2 * tg]);
            a[mt][2] = *reinterpret_cast<const unsigned*>(&As[buf][r0][ks + 8 + 2 * tg]);
            a[mt][3] = *reinterpret_cast<const unsigned*>(&As[buf][r0 + 8][ks + 8 + 2 * tg]);
        }
        unsigned bf[4][2];
#pragma unroll
        for (int nt = 0; nt < 4; ++nt) {
            int n0 = wn + nt * 8 + g;
            bf[nt][0] = *reinterpret_cast<const unsigned*>(&Bs[buf][n0][ks + 2 * tg]);
            bf[nt][1] = *reinterpret_cast<const unsigned*>(&Bs[buf][n0][ks + 8 + 2 * tg]);
        }
#pragma unroll
        for (int mt = 0; mt < 2; ++mt)
#pragma unroll
            for (int nt = 0; nt < 4; ++nt)
                MMA_F16(acc[mt][nt], a[mt], bf[nt]);

        if (kt + 1 < nk) { __syncthreads(); sts((kt + 1) & 1); }
        __syncthreads();
    }

    // k-group 1 stages its partials; k-group 0 reduces and writes
    if (kg == 1) {
#pragma unroll
        for (int mt = 0; mt < 2; ++mt)
#pragma unroll
            for (int nt = 0; nt < 4; ++nt)
#pragma unroll
                for (int r = 0; r < 4; ++r) {
                    int row = wm + mt * 16 + g + ((r >> 1) << 3);
                    int col = wn + nt * 8 + 2 * tg + (r & 1);
                    red[row][col] = acc[mt][nt][r];
                }
    }
    __syncthreads();
    if (kg == 0) {
#pragma unroll
        for (int mt = 0; mt < 2; ++mt)
#pragma unroll
            for (int nt = 0; nt < 4; ++nt)
#pragma unroll
                for (int r = 0; r < 4; ++r) {
                    int rl = wm + mt * 16 + g + ((r >> 1) << 3);
                    int cl = wn + nt * 8 + 2 * tg + (r & 1);
                    int row = bm + rl, col = bn + cl;
                    if (row < M && col < N) {
                        float v = acc[mt][nt][r] + red[rl][cl];
                        if (bias) v += bias[col];
                        if (Ch) Ch[(size_t)row * ldc + col] = __float2half_rn(v);
                        else    C [(size_t)row * ldc + col] = v;
                    }
                }
    }
}

// ---------------- split-K gates GEMM + fused LSTM (256 threads) ----------------
__global__ __launch_bounds__(256)
void gemm_gates_sk(const __half* __restrict__ A, const __half* __restrict__ B,
                   const float* __restrict__ bg, const float* __restrict__ Y,
                   const float* __restrict__ WohT, const int* __restrict__ text, int s,
                   float* __restrict__ c, __half* __restrict__ h_h,
                   __half* __restrict__ outh_h)
{
    __shared__ __half As[2][64][SMP];
    __shared__ __half Bs[2][64][SMP];
    __shared__ float gsm[64][68];

    const int tid  = threadIdx.x;
    const int bm   = blockIdx.x * 64;
    const int bn   = blockIdx.y * 64;
    const int w    = tid >> 5, lane = tid & 31;
    const int g    = lane >> 2, tg = lane & 3;
    const int kg   = w >> 2;
    const int ws   = w & 3;
    const int wm   = (ws & 1) * 32;
    const int wn   = (ws >> 1) * 32;
    const int ks   = kg << 4;

    float acc[2][4][4];
#pragma unroll
    for (int mt = 0; mt < 2; ++mt)
#pragma unroll
        for (int nt = 0; nt < 4; ++nt)
#pragma unroll
            for (int r = 0; r < 4; ++r) acc[mt][nt][r] = 0.f;

    uint4 stA, stB;
    const int nk = II >> 5;
    const int kld = II >> 3;
    const int lr = tid >> 2, lc = tid & 3;

    auto ldg = [&](int k0) {
        stA = *(reinterpret_cast<const uint4*>(A) + (size_t)(bm + lr) * kld + (k0 >> 3) + lc);
        stB = *(reinterpret_cast<const uint4*>(B) + (size_t)(bn + lr) * kld + (k0 >> 3) + lc);
    };
    auto sts = [&](int buf) {
        *reinterpret_cast<uint4*>(&As[buf][lr][lc * 8]) = stA;
        *reinterpret_cast<uint4*>(&Bs[buf][lr][lc * 8]) = stB;
    };

    ldg(0); sts(0);
    __syncthreads();

    for (int kt = 0; kt < nk; ++kt) {
        const int buf = kt & 1;
        if (kt + 1 < nk) ldg((kt + 1) << 5);

        unsigned a[2][4];
#pragma unroll
        for (int mt = 0; mt < 2; ++mt) {
            int r0 = wm + mt * 16 + g;
            a[mt][0] = *reinterpret_cast<const unsigned*>(&As[buf][r0][ks + 2 * tg]);
            a[mt][1] = *reinterpret_cast<const unsigned*>(&As[buf][r0 + 8][ks + 2 * tg]);
            a[mt][2] = *reinterpret_cast<const unsigned*>(&As[buf][r0][ks + 8 + 2 * tg]);
            a[mt][3] = *reinterpret_cast<const unsigned*>(&As[buf][r0 + 8][ks + 8 + 2 * tg]);
        }
        unsigned bf[4][2];
#pragma unroll
        for (int nt = 0; nt < 4; ++nt) {
            int n0 = wn + nt * 8 + g;
            bf[nt][0] = *reinterpret_cast<const unsigned*>(&Bs[buf][n0][ks + 2 * tg]);
            bf[nt][1] = *reinterpret_cast<const unsigned*>(&Bs[buf][n0][ks + 8 + 2 * tg]);
        }
#pragma unroll
        for (int mt = 0; mt < 2; ++mt)
#pragma unroll
            for (int nt = 0; nt < 4; ++nt)
                MMA_F16(acc[mt][nt], a[mt], bf[nt]);

        if (kt + 1 < nk) { __syncthreads(); sts((kt + 1) & 1); }
        __syncthreads();
    }

    // reduce the two k-groups into gsm
    if (kg == 1) {
#pragma unroll
        for (int mt = 0; mt < 2; ++mt)
#pragma unroll
            for (int nt = 0; nt < 4; ++nt)
#pragma unroll
                for (int r = 0; r < 4; ++r) {
                    int rl = wm + mt * 16 + g + ((r >> 1) << 3);
                    int cl = wn + nt * 8 + 2 * tg + (r & 1);
                    gsm[rl][cl] = acc[mt][nt][r];
                }
    }
    __syncthreads();
    if (kg == 0) {
#pragma unroll
        for (int mt = 0; mt < 2; ++mt)
#pragma unroll
            for (int nt = 0; nt < 4; ++nt)
#pragma unroll
                for (int r = 0; r < 4; ++r) {
                    int rl = wm + mt * 16 + g + ((r >> 1) << 3);
                    int cl = wn + nt * 8 + 2 * tg + (r & 1);
                    gsm[rl][cl] += acc[mt][nt][r];
                }
    }
    __syncthreads();

    // fused LSTM: 256 threads x 4 (row, unit) items
    {
        const int r  = tid >> 2;            // local row 0..63
        const int u0 = tid & 3;
        const int b  = bm + r;
        const int cls = text[b * SS + s];
        const float4* wo4 = reinterpret_cast<const float4*>(WohT + (size_t)cls * G4H + bn);
        const float4* bg4 = reinterpret_cast<const float4*>(bg + bn);
        const float4* Y4  = reinterpret_cast<const float4*>(Y + (size_t)b * NCOMB + HH + bn);
#pragma unroll
        for (int j = 0; j < 4; ++j) {
            int u = 4 * j + u0;             // 0..15
            float4 gv = *reinterpret_cast<const float4*>(&gsm[r][4 * u]);
            float4 bv = bg4[u];
            float4 yv = Y4[u];
            float4 wv = wo4[u];
            float gi = gv.x + bv.x + yv.x + wv.x;
            float gf = gv.y + bv.y + yv.y + wv.y;
            float gg = gv.z + bv.z + yv.z + wv.z;
            float go = gv.w + bv.w + yv.w + wv.w;

            int ug = (bn >> 2) + u;
            int cidx = b * HH + ug;
            float ci = c[cidx];
            float ig = 1.f / (1.f + expf(-gi));
            float fg = 1.f / (1.f + expf(-gf));
            float og = 1.f / (1.f + expf(-go));
            float c2 = fg * ci + ig * tanhf(gg);
            float h2 = og * tanhf(c2);

            c[cidx] = c2;
            __half h2h = __float2half_rn(h2);
            h_h[cidx] = h2h;
            outh_h[((size_t)b * SS + s) * HH + ug] = h2h;
        }
    }
}

// ---------------- fp16 GEMM, 128x128 tile, 256 threads (feat) ----------------
#define SMPB 40

__global__ __launch_bounds__(256)
void gemm_f16_big(const __half* __restrict__ A, const __half* __restrict__ B,
                  float* __restrict__ C, __half* __restrict__ Ch,
                  int M, int N, int K, int ldc)
{
    __shared__ __half As[2][128][SMPB];
    __shared__ __half Bs[2][128][SMPB];

    const int tid  = threadIdx.x;
    const int bm   = blockIdx.x * 128;
    const int bn   = blockIdx.y * 128;
    const int w    = tid >> 5, lane = tid & 31;
    const int g    = lane >> 2, tg = lane & 3;
    const int wm   = (w & 1) * 64;
    const int wn   = (w >> 1) * 32;

    float acc[4][4][4];
#pragma unroll
    for (int mt = 0; mt < 4; ++mt)
#pragma unroll
        for (int nt = 0; nt < 4; ++nt)
#pragma unroll
            for (int r = 0; r < 4; ++r) acc[mt][nt][r] = 0.f;

    uint4 stA[2], stB[2];
    const uint4 z4 = make_uint4(0u, 0u, 0u, 0u);
    const int nk = K >> 5;
    const int kld = K >> 3;

    auto ldg = [&](int k0) {
#pragma unroll
        for (int i = 0; i < 2; ++i) {
            int id = tid + i * 256;
            int r = id >> 2, cg = id & 3;
            const uint4* Ar = reinterpret_cast<const uint4*>(A) + (size_t)(bm + r) * kld + (k0 >> 3) + cg;
            const uint4* Br = reinterpret_cast<const uint4*>(B) + (size_t)(bn + r) * kld + (k0 >> 3) + cg;
            stA[i] = (bm + r < M) ? *Ar : z4;
            stB[i] = (bn + r < N) ? *Br : z4;
        }
    };
    auto sts = [&](int buf) {
#pragma unroll
        for (int i = 0; i < 2; ++i) {
            int id = tid + i * 256;
            int r = id >> 2, cg = id & 3;
            *reinterpret_cast<uint4*>(&As[buf][r][cg * 8]) = stA[i];
            *reinterpret_cast<uint4*>(&Bs[buf][r][cg * 8]) = stB[i];
        }
    };

    ldg(0); sts(0);
    __syncthreads();

    for (int kt = 0; kt < nk; ++kt) {
        const int buf = kt & 1;
        if (kt + 1 < nk) ldg((kt + 1) << 5);

#pragma unroll
        for (int ks = 0; ks < 32; ks += 16) {
            unsigned a[4][4];
#pragma unroll
            for (int mt = 0; mt < 4; ++mt) {
                int r0 = wm + mt * 16 + g;
                a[mt][0] = *reinterpret_cast<const unsigned*>(&As[buf][r0][ks + 2 * tg]);
                a[mt][1] = *reinterpret_cast<const unsigned*>(&As[buf][r0 + 8][ks + 2 * tg]);
                a[mt][2] = *reinterpret_cast<const unsigned*>(&As[buf][r0][ks + 8 + 2 * tg]);
                a[mt][3] = *reinterpret_cast<const unsigned*>(&As[buf][r0 + 8][ks + 8 + 2 * tg]);
            }
            unsigned bf[4][2];
#pragma unroll
            for (int nt = 0; nt < 4; ++nt) {
                int n0 = wn + nt * 8 + g;
                bf[nt][0] = *reinterpret_cast<const unsigned*>(&Bs[buf][n0][ks + 2 * tg]);
                bf[nt][1] = *reinterpret_cast<const unsigned*>(&Bs[buf][n0][ks + 8 + 2 * tg]);
            }
#pragma unroll
            for (int mt = 0; mt < 4; ++mt)
#pragma unroll
                for (int nt = 0; nt < 4; ++nt)
                    MMA_F16(acc[mt][nt], a[mt], bf[nt]);
        }

        if (kt + 1 < nk) { __syncthreads(); sts((kt + 1) & 1); }
        __syncthreads();
    }

#pragma unroll
    for (int mt = 0; mt < 4; ++mt)
#pragma unroll
        for (int nt = 0; nt < 4; ++nt)
#pragma unroll
            for (int r = 0; r < 4; ++r) {
                int row = bm + wm + mt * 16 + g + ((r >> 1) << 3);
                int col = bn + wn + nt * 8 + 2 * tg + (r & 1);
                if (row < M && col < N) {
                    float v = acc[mt][nt][r];
                    if (Ch) Ch[(size_t)row * ldc + col] = __float2half_rn(v);
                    else    C [(size_t)row * ldc + col] = v;
                }
            }
}

// ---------------- attention energies (grid 512 x 2, 256 threads) ----------------
// block (b, thalf) computes e[b, thalf*64 .. +64)
__global__ __launch_bounds__(256)
void att_energy(const uint4* __restrict__ F4,
                const float* __restrict__ hp, int hp_ld,
                const float* __restrict__ w_score, float* __restrict__ e_out)
{
    const int b = blockIdx.x;
    const int tbase = blockIdx.y * 64;
    const int tid = threadIdx.x;
    const int warp = tid >> 5, lane = tid & 31;

    float2 hpv[8], wsv[8];
    {
        const float2* hp2 = reinterpret_cast<const float2*>(hp + (size_t)b * hp_ld);
        const float2* ws2 = reinterpret_cast<const float2*>(w_score);
#pragma unroll
        for (int j = 0; j < 2; ++j)
#pragma unroll
            for (int q = 0; q < 4; ++q) {
                int idx = 4 * (j * 32 + lane) + q;
                hpv[j * 4 + q] = hp2[idx];
                wsv[j * 4 + q] = ws2[idx];
            }
    }

#pragma unroll
    for (int it = 0; it < 4; ++it) {
        const int t0 = tbase + it * 16 + warp;
        const int t1 = t0 + 8;
        const uint4* f0 = F4 + ((size_t)b * TT + t0) * 64;
        const uint4* f1 = F4 + ((size_t)b * TT + t1) * 64;
        uint4 u0a = f0[lane], u0b = f0[32 + lane];
        uint4 u1a = f1[lane], u1b = f1[32 + lane];
        float acc0 = 0.f, acc1 = 0.f;
#pragma unroll
        for (int q = 0; q < 4; ++q) {
            {
                float2 f = __half22float2(reinterpret_cast<const __half2*>(&u0a)[q]);
                float2 hv = hpv[q], wv = wsv[q];
                float a0, a1;
                asm("tanh.approx.f32 %0, %1;" : "=f"(a0) : "f"(f.x + hv.x));
                asm("tanh.approx.f32 %0, %1;" : "=f"(a1) : "f"(f.y + hv.y));
                acc0 = fmaf(a0, wv.x, fmaf(a1, wv.y, acc0));
            }
            {
                float2 f = __half22float2(reinterpret_cast<const __half2*>(&u0b)[q]);
                float2 hv = hpv[4 + q], wv = wsv[4 + q];
                float a0, a1;
                asm("tanh.approx.f32 %0, %1;" : "=f"(a0) : "f"(f.x + hv.x));
                asm("tanh.approx.f32 %0, %1;" : "=f"(a1) : "f"(f.y + hv.y));
                acc0 = fmaf(a0, wv.x, fmaf(a1, wv.y, acc0));
            }
            {
                float2 f = __half22float2(reinterpret_cast<const __half2*>(&u1a)[q]);
                float2 hv = hpv[q], wv = wsv[q];
                float a0, a1;
                asm("tanh.approx.f32 %0, %1;" : "=f"(a0) : "f"(f.x + hv.x));
                asm("tanh.approx.f32 %0, %1;" : "=f"(a1) : "f"(f.y + hv.y));
                acc1 = fmaf(a0, wv.x, fmaf(a1, wv.y, acc1));
            }
            {
                float2 f = __half22float2(reinterpret_cast<const __half2*>(&u1b)[q]);
                float2 hv = hpv[4 + q], wv = wsv[4 + q];
                float a0, a1;
                asm("tanh.approx.f32 %0, %1;" : "=f"(a0) : "f"(f.x + hv.x));
                asm("tanh.approx.f32 %0, %1;" : "=f"(a1) : "f"(f.y + hv.y));
                acc1 = fmaf(a0, wv.x, fmaf(a1, wv.y, acc1));
            }
        }
#pragma unroll
        for (int o = 16; o > 0; o >>= 1) {
            acc0 += __shfl_xor_sync(0xffffffffu, acc0, o);
            acc1 += __shfl_xor_sync(0xffffffffu, acc1, o);
        }
        if (lane == 0) { e_out[b * TT + t0] = acc0; e_out[b * TT + t1] = acc1; }
    }
}

// ---------------- attention softmax + context (grid 512 x 2, 256 threads) ----------------
// block (b, ihalf) computes ctx[b, ihalf*256 .. +256) ; softmax recomputed per block
__global__ __launch_bounds__(256)
void att_ctx(const uint4* __restrict__ H4, const float* __restrict__ e,
             __half2* __restrict__ ctx)
{
    __shared__ float e_sh[TT];
    __shared__ float red_sh[2];
    __shared__ float red8[8][32][8];

    const int b = blockIdx.x;
    const int ih = blockIdx.y;
    const int tid = threadIdx.x;

    if (tid < TT) e_sh[tid] = e[b * TT + tid];
    __syncthreads();

    if (tid < 32) {
        float m = fmaxf(fmaxf(e_sh[tid], e_sh[tid + 32]),
                        fmaxf(e_sh[tid + 64], e_sh[tid + 96]));
#pragma unroll
        for (int o = 16; o > 0; o >>= 1) m = fmaxf(m, __shfl_xor_sync(0xffffffffu, m, o));
        if (tid == 0) red_sh[0] = m;
    }
    __syncthreads();
    const float mx = red_sh[0];
    if (tid < TT) e_sh[tid] = __expf(e_sh[tid] - mx);
    __syncthreads();
    if (tid < 32) {
        float ssum = e_sh[tid] + e_sh[tid + 32] + e_sh[tid + 64] + e_sh[tid + 96];
#pragma unroll
        for (int o = 16; o > 0; o >>= 1) ssum += __shfl_xor_sync(0xffffffffu, ssum, o);
        if (tid == 0) red_sh[1] = 1.f / ssum;
    }
    __syncthreads();

    // context partials: 8 t-groups of 32 threads, 16 t each; thread covers 1 uint4 (8 cols)
    {
        const int tg8 = tid >> 5, lane = tid & 31;
        const uint4* Hb = H4 + (size_t)b * TT * 64 + ih * 32 + lane;
        float acc[8];
#pragma unroll
        for (int q = 0; q < 8; ++q) acc[q] = 0.f;
        const int tbeg = tg8 * 16;
#pragma unroll 4
        for (int t = tbeg; t < tbeg + 16; ++t) {
            uint4 u = Hb[(size_t)t * 64];
            float a = e_sh[t];
#pragma unroll
            for (int q = 0; q < 4; ++q) {
                float2 v = __half22float2(reinterpret_cast<const __half2*>(&u)[q]);
                acc[2 * q]     = fmaf(a, v.x, acc[2 * q]);
                acc[2 * q + 1] = fmaf(a, v.y, acc[2 * q + 1]);
            }
        }
#pragma unroll
        for (int q = 0; q < 8; ++q) red8[tg8][lane][q] = acc[q];
    }
    __syncthreads();

    // final combine: 128 threads x 1 half2 output each
    if (tid < 128) {
        const float inv = red_sh[1];
        const int lane2 = tid >> 2, qp = tid & 3;
        float x = 0.f, y = 0.f;
#pragma unroll
        for (int gi = 0; gi < 8; ++gi) {
            x += red8[gi][lane2][2 * qp];
            y += red8[gi][lane2][2 * qp + 1];
        }
        ctx[(size_t)b * (II / 2) + (ih * 32 + lane2) * 4 + qp] =
            __float22half2_rn(make_float2(x * inv, y * inv));
    }
}

// ---------------- host launcher ----------------
extern "C" void kernel_launch(void* const* d_in, const int* in_sizes, int n_in,
                              void* d_out, int out_size)
{
    const float* batch_H = (const float*)d_in[0];
    const int*   text    = (const int*)  d_in[1];
    const float* W_feat  = (const float*)d_in[2];
    const float* W_hid   = (const float*)d_in[3];
    const float* b_hid   = (const float*)d_in[4];
    const float* w_score = (const float*)d_in[5];
    const float* W_ih    = (const float*)d_in[6];
    const float* W_hh    = (const float*)d_in[7];
    const float* b_ih    = (const float*)d_in[8];
    const float* b_hh    = (const float*)d_in[9];
    const float* W_gen   = (const float*)d_in[10];
    const float* b_gen   = (const float*)d_in[11];
    float* out = (float*)d_out;

    float *c, *Y, *e, *WohT, *bg, *bcomb;
    __half2 *feat_h, *H_h, *ctx_h;
    __half *h_h, *outh_h, *Wx_h, *Wcomb_h, *Wfeat_h, *Wgen_h;
    cudaGetSymbolAddress((void**)&feat_h,  g_feat_h);
    cudaGetSymbolAddress((void**)&H_h,     g_H_h);
    cudaGetSymbolAddress((void**)&h_h,     g_h_h);
    cudaGetSymbolAddress((void**)&c,       g_c);
    cudaGetSymbolAddress((void**)&Y,       g_Y);
    cudaGetSymbolAddress((void**)&e,       g_e);
    cudaGetSymbolAddress((void**)&ctx_h,   g_ctx_h);
    cudaGetSymbolAddress((void**)&outh_h,  g_outh_h);
    cudaGetSymbolAddress((void**)&Wx_h,    g_Wx_h);
    cudaGetSymbolAddress((void**)&Wcomb_h, g_Wcomb_h);
    cudaGetSymbolAddress((void**)&Wfeat_h, g_Wfeat_h);
    cudaGetSymbolAddress((void**)&Wgen_h,  g_Wgen_h);
    cudaGetSymbolAddress((void**)&bcomb,   g_bcomb);
    cudaGetSymbolAddress((void**)&WohT,    g_WohT);
    cudaGetSymbolAddress((void**)&bg,      g_bg);

    // pack weights (fp16, gate-interleaved) + fp16 batch_H + zero state
    pack_kernel<<<512, 256>>>(W_ih, b_ih, b_hh, W_hid, W_hh, b_hid,
                              W_feat, W_gen, batch_H);

    // feat[BT, H] = batch_H @ W_feat^T  -> fp16
    gemm_f16_big<<<dim3((BB * TT) / 128, HH / 128), 256>>>(
        (const __half*)H_h, Wfeat_h, nullptr, (__half*)feat_h,
        BB * TT, HH, II, HH);

    for (int s = 0; s < SS; ++s) {
        // Y = h @ [W_hid ; W_hh_il]^T + [b_hid ; 0]   -> [B, 2560] fp32
        gemm_f16_sk<<<dim3(BB / 64, NCOMB / 64), 256>>>(
            h_h, Wcomb_h, bcomb, Y, nullptr, BB, NCOMB, HH, NCOMB);

        // attention energies (hp = Y[:, :512]) -> e
        att_energy<<<dim3(BB, 2), 256>>>((const uint4*)feat_h, Y, NCOMB, w_score, e);

        // softmax + context -> fp16 ctx
        att_ctx<<<dim3(BB, 2), 256>>>((const uint4*)H_h, e, ctx_h);

        // gates GEMM + fused LSTM cell
        gemm_gates_sk<<<dim3(BB / 64, G4H / 64), 256>>>(
            (const __half*)ctx_h, Wx_h, bg, Y, WohT, text, s, c, h_h, outh_h);
    }

    // probs[B*S, C] = outh @ W_gen^T + b_gen
    gemm_f16_sk<<<dim3((BB * SS) / 64, (CC + 63) / 64), 256>>>(
        outh_h, Wgen_h, b_gen, out, nullptr, BB * SS, CC, HH, CC);
}

// round 11
// speedup vs baseline: 1.0842x; 1.0842x over previous
#include <cuda_runtime.h>
#include <cuda_bf16.h>
#include <cuda_fp16.h>
#include <cstdint>

// Problem constants
#define BB 512
#define TT 128
#define II 512
#define HH 512
#define CC 97
#define SS 26
#define G4H 2048           // 4*H
#define NCOMB 2560         // H + 4H
#define WIH_LD 609         // I + C

// Interleaved gate index: m = 4*u + g  <->  original row g*512 + u

// ---------------- device scratch (static, no allocs) ----------------
__device__ __half2 g_feat_h[(size_t)BB * TT * HH / 2];   // 64 MB fp16 feat
__device__ __half2 g_H_h[(size_t)BB * TT * II / 2];      // 64 MB fp16 batch_H
__device__ __half  g_h_h[BB * HH];                       // fp16 hidden state
__device__ float   g_c[BB * HH];
__device__ float   g_Y[BB * NCOMB];                      // [hp | h@Whh_il^T] fp32
__device__ __half2 g_ctx_h[BB * II / 2];                 // fp16 context
__device__ __half  g_outh_h[(size_t)BB * SS * HH];       // fp16 step outputs
__device__ __half  g_Wx_h[G4H * II];                     // W_ih[:, :I], gate-interleaved
__device__ __half  g_Wcomb_h[NCOMB * HH];                // [W_hid ; W_hh interleaved]
__device__ __half  g_Wfeat_h[HH * II];
__device__ __half  g_Wgen_h[CC * HH];
__device__ float   g_bcomb[NCOMB];                       // [b_hid ; 0]
__device__ float   g_WohT[CC * G4H];                     // W_ih[:, I:]^T interleaved
__device__ float   g_bg[G4H];                            // (b_ih + b_hh) interleaved

// ---------------- pack / init kernel ----------------
__global__ void pack_kernel(const float* __restrict__ W_ih,
                            const float* __restrict__ b_ih,
                            const float* __restrict__ b_hh,
                            const float* __restrict__ W_hid,
                            const float* __restrict__ W_hh,
                            const float* __restrict__ b_hid,
                            const float* __restrict__ W_feat,
                            const float* __restrict__ W_gen,
                            const float* __restrict__ batch_H)
{
    const int stride = gridDim.x * blockDim.x;
    const int t0 = blockIdx.x * blockDim.x + threadIdx.x;
    for (int i = t0; i < G4H * II; i += stride) {
        int n = i >> 9, k = i & 511;
        int u = n >> 2, g = n & 3;
        g_Wx_h[i] = __float2half_rn(W_ih[(g * 512 + u) * WIH_LD + k]);
    }
    for (int i = t0; i < NCOMB * HH; i += stride) {
        int n = i >> 9, k = i & 511;
        float v;
        if (n < HH) v = W_hid[n * HH + k];
        else {
            int m = n - HH, u = m >> 2, g = m & 3;
            v = W_hh[(g * 512 + u) * HH + k];
        }
        g_Wcomb_h[i] = __float2half_rn(v);
    }
    for (int i = t0; i < HH * II; i += stride)
        g_Wfeat_h[i] = __float2half_rn(W_feat[i]);
    for (int i = t0; i < CC * HH; i += stride)
        g_Wgen_h[i] = __float2half_rn(W_gen[i]);
    for (int i = t0; i < CC * G4H; i += stride) {
        int cls = i >> 11, m = i & 2047;
        int u = m >> 2, g = m & 3;
        g_WohT[i] = W_ih[(g * 512 + u) * WIH_LD + II + cls];
    }
    for (int i = t0; i < G4H; i += stride) {
        int u = i >> 2, g = i & 3;
        g_bg[i] = b_ih[g * 512 + u] + b_hh[g * 512 + u];
    }
    for (int i = t0; i < NCOMB; i += stride) g_bcomb[i] = (i < HH) ? b_hid[i] : 0.f;
    for (int i = t0; i < BB * HH; i += stride) {
        g_h_h[i] = __float2half_rn(0.f);
        g_c[i] = 0.f;
    }
    const size_t nh2 = (size_t)BB * TT * II / 2;
    const float2* src = reinterpret_cast<const float2*>(batch_H);
    for (size_t i = t0; i < nh2; i += stride)
        g_H_h[i] = __float22half2_rn(src[i]);
}

#define MMA_F16(d, a, b)                                                         \
    asm volatile("mma.sync.aligned.m16n8k16.row.col.f32.f16.f16.f32 "            \
                 "{%0,%1,%2,%3}, {%4,%5,%6,%7}, {%8,%9}, {%0,%1,%2,%3};"         \
                 : "+f"(d[0]), "+f"(d[1]), "+f"(d[2]), "+f"(d[3])                \
                 : "r"(a[0]), "r"(a[1]), "r"(a[2]), "r"(a[3]),                   \
                   "r"(b[0]), "r"(b[1]))

#define SMP 56

// ---------------- split-K fp16 GEMM, 64x64 tile, 256 threads ----------------
// 8 warps: 2x2 warp tiles x 2 K-groups; smem reduction at the end.
__global__ __launch_bounds__(256)
void gemm_f16_sk(const __half* __restrict__ A, const __half* __restrict__ B,
                 const float* __restrict__ bias, float* __restrict__ C,
                 __half* __restrict__ Ch,
                 int M, int N, int K, int ldc)
{
    __shared__ __half As[2][64][SMP];
    __shared__ __half Bs[2][64][SMP];
    __shared__ float red[64][65];

    const int tid  = threadIdx.x;
    const int bm   = blockIdx.x * 64;
    const int bn   = blockIdx.y * 64;
    const int w    = tid >> 5, lane = tid & 31;
    const int g    = lane >> 2, tg = lane & 3;
    const int kg   = w >> 2;
    const int ws   = w & 3;
    const int wm   = (ws & 1) * 32;
    const int wn   = (ws >> 1) * 32;
    const int ks   = kg << 4;

    float acc[2][4][4];
#pragma unroll
    for (int mt = 0; mt < 2; ++mt)
#pragma unroll
        for (int nt = 0; nt < 4; ++nt)
#pragma unroll
            for (int r = 0; r < 4; ++r) acc[mt][nt][r] = 0.f;

    uint4 stA, stB;
    const uint4 z4 = make_uint4(0u, 0u, 0u, 0u);
    const int nk = K >> 5;
    const int kld = K >> 3;
    const int lr = tid >> 2, lc = tid & 3;

    auto ldg = [&](int k0) {
        const uint4* Ar = reinterpret_cast<const uint4*>(A) + (size_t)(bm + lr) * kld + (k0 >> 3) + lc;
        const uint4* Br = reinterpret_cast<const uint4*>(B) + (size_t)(bn + lr) * kld + (k0 >> 3) + lc;
        stA = (bm + lr < M) ? *Ar : z4;
        stB = (bn + lr < N) ? *Br : z4;
    };
    auto sts = [&](int buf) {
        *reinterpret_cast<uint4*>(&As[buf][lr][lc * 8]) = stA;
        *reinterpret_cast<uint4*>(&Bs[buf][lr][lc * 8]) = stB;
    };

    ldg(0); sts(0);
    __syncthreads();

    for (int kt = 0; kt < nk; ++kt) {
        const int buf = kt & 1;
        if (kt + 1 < nk) ldg((kt + 1) << 5);

        unsigned a[2][4];
#pragma unroll
        for (int mt = 0; mt < 2; ++mt) {
            int r0 = wm + mt * 16 + g;
            a[mt][0] = *reinterpret_cast<const unsigned*>(&As[buf][r0][ks + 2 * tg]);
            a[mt][1] = *reinterpret_cast<const unsigned*>(&As[buf][r0 + 8][ks + 2 * tg]);
            a[mt][2] = *reinterpret_cast<const unsigned*>(&As[buf][r0][ks + 8 + 2 * tg]);
            a[mt][3] = *reinterpret_cast<const unsigned*>(&As[buf][r0 + 8][ks + 8 + 2 * tg]);
        }
        unsigned bf[4][2];
#pragma unroll
        for (int nt = 0; nt < 4; ++nt) {
            int n0 = wn + nt * 8 + g;
            bf[nt][0] = *reinterpret_cast<const unsigned*>(&Bs[buf][n0][ks + 2 * tg]);
            bf[nt][1] = *reinterpret_cast<const unsigned*>(&Bs[buf][n0][ks + 8 + 2 * tg]);
        }
#pragma unroll
        for (int mt = 0; mt < 2; ++mt)
#pragma unroll
            for (int nt = 0; nt < 4; ++nt)
                MMA_F16(acc[mt][nt], a[mt], bf[nt]);

        if (kt + 1 < nk) { __syncthreads(); sts((kt + 1) & 1); }
        __syncthreads();
    }

    // k-group 1 stages its partials; k-group 0 reduces and writes
    if (kg == 1) {
#pragma unroll
        for (int mt = 0; mt < 2; ++mt)
#pragma unroll
            for (int nt = 0; nt < 4; ++nt)
#pragma unroll
                for (int r = 0; r < 4; ++r) {
                    int row = wm + mt * 16 + g + ((r >> 1) << 3);
                    int col = wn + nt * 8 + 2 * tg + (r & 1);
                    red[row][col] = acc[mt][nt][r];
                }
    }
    __syncthreads();
    if (kg == 0) {
#pragma unroll
        for (int mt = 0; mt < 2; ++mt)
#pragma unroll
            for (int nt = 0; nt < 4; ++nt)
#pragma unroll
                for (int r = 0; r < 4; ++r) {
                    int rl = wm + mt * 16 + g + ((r >> 1) << 3);
                    int cl = wn + nt * 8 + 2 * tg + (r & 1);
                    int row = bm + rl, col = bn + cl;
                    if (row < M && col < N) {
                        float v = acc[mt][nt][r] + red[rl][cl];
                        if (bias) v += bias[col];
                        if (Ch) Ch[(size_t)row * ldc + col] = __float2half_rn(v);
                        else    C [(size_t)row * ldc + col] = v;
                    }
                }
    }
}

// ---------------- split-K gates GEMM + fused LSTM (256 threads) ----------------
__global__ __launch_bounds__(256)
void gemm_gates_sk(const __half* __restrict__ A, const __half* __restrict__ B,
                   const float* __restrict__ bg, const float* __restrict__ Y,
                   const float* __restrict__ WohT, const int* __restrict__ text, int s,
                   float* __restrict__ c, __half* __restrict__ h_h,
                   __half* __restrict__ outh_h)
{
    __shared__ __half As[2][64][SMP];
    __shared__ __half Bs[2][64][SMP];
    __shared__ float gsm[64][68];

    const int tid  = threadIdx.x;
    const int bm   = blockIdx.x * 64;
    const int bn   = blockIdx.y * 64;
    const int w    = tid >> 5, lane = tid & 31;
    const int g    = lane >> 2, tg = lane & 3;
    const int kg   = w >> 2;
    const int ws   = w & 3;
    const int wm   = (ws & 1) * 32;
    const int wn   = (ws >> 1) * 32;
    const int ks   = kg << 4;

    float acc[2][4][4];
#pragma unroll
    for (int mt = 0; mt < 2; ++mt)
#pragma unroll
        for (int nt = 0; nt < 4; ++nt)
#pragma unroll
            for (int r = 0; r < 4; ++r) acc[mt][nt][r] = 0.f;

    uint4 stA, stB;
    const int nk = II >> 5;
    const int kld = II >> 3;
    const int lr = tid >> 2, lc = tid & 3;

    auto ldg = [&](int k0) {
        stA = *(reinterpret_cast<const uint4*>(A) + (size_t)(bm + lr) * kld + (k0 >> 3) + lc);
        stB = *(reinterpret_cast<const uint4*>(B) + (size_t)(bn + lr) * kld + (k0 >> 3) + lc);
    };
    auto sts = [&](int buf) {
        *reinterpret_cast<uint4*>(&As[buf][lr][lc * 8]) = stA;
        *reinterpret_cast<uint4*>(&Bs[buf][lr][lc * 8]) = stB;
    };

    ldg(0); sts(0);
    __syncthreads();

    for (int kt = 0; kt < nk; ++kt) {
        const int buf = kt & 1;
        if (kt + 1 < nk) ldg((kt + 1) << 5);

        unsigned a[2][4];
#pragma unroll
        for (int mt = 0; mt < 2; ++mt) {
            int r0 = wm + mt * 16 + g;
            a[mt][0] = *reinterpret_cast<const unsigned*>(&As[buf][r0][ks + 2 * tg]);
            a[mt][1] = *reinterpret_cast<const unsigned*>(&As[buf][r0 + 8][ks + 2 * tg]);
            a[mt][2] = *reinterpret_cast<const unsigned*>(&As[buf][r0][ks + 8 + 2 * tg]);
            a[mt][3] = *reinterpret_cast<const unsigned*>(&As[buf][r0 + 8][ks + 8 + 2 * tg]);
        }
        unsigned bf[4][2];
#pragma unroll
        for (int nt = 0; nt < 4; ++nt) {
            int n0 = wn + nt * 8 + g;
            bf[nt][0] = *reinterpret_cast<const unsigned*>(&Bs[buf][n0][ks + 2 * tg]);
            bf[nt][1] = *reinterpret_cast<const unsigned*>(&Bs[buf][n0][ks + 8 + 2 * tg]);
        }
#pragma unroll
        for (int mt = 0; mt < 2; ++mt)
#pragma unroll
            for (int nt = 0; nt < 4; ++nt)
                MMA_F16(acc[mt][nt], a[mt], bf[nt]);

        if (kt + 1 < nk) { __syncthreads(); sts((kt + 1) & 1); }
        __syncthreads();
    }

    // reduce the two k-groups into gsm
    if (kg == 1) {
#pragma unroll
        for (int mt = 0; mt < 2; ++mt)
#pragma unroll
            for (int nt = 0; nt < 4; ++nt)
#pragma unroll
                for (int r = 0; r < 4; ++r) {
                    int rl = wm + mt * 16 + g + ((r >> 1) << 3);
                    int cl = wn + nt * 8 + 2 * tg + (r & 1);
                    gsm[rl][cl] = acc[mt][nt][r];
                }
    }
    __syncthreads();
    if (kg == 0) {
#pragma unroll
        for (int mt = 0; mt < 2; ++mt)
#pragma unroll
            for (int nt = 0; nt < 4; ++nt)
#pragma unroll
                for (int r = 0; r < 4; ++r) {
                    int rl = wm + mt * 16 + g + ((r >> 1) << 3);
                    int cl = wn + nt * 8 + 2 * tg + (r & 1);
                    gsm[rl][cl] += acc[mt][nt][r];
                }
    }
    __syncthreads();

    // fused LSTM: 256 threads x 4 (row, unit) items
    {
        const int r  = tid >> 2;            // local row 0..63
        const int u0 = tid & 3;
        const int b  = bm + r;
        const int cls = text[b * SS + s];
        const float4* wo4 = reinterpret_cast<const float4*>(WohT + (size_t)cls * G4H + bn);
        const float4* bg4 = reinterpret_cast<const float4*>(bg + bn);
        const float4* Y4  = reinterpret_cast<const float4*>(Y + (size_t)b * NCOMB + HH + bn);
#pragma unroll
        for (int j = 0; j < 4; ++j) {
            int u = 4 * j + u0;             // 0..15
            float4 gv = *reinterpret_cast<const float4*>(&gsm[r][4 * u]);
            float4 bv = bg4[u];
            float4 yv = Y4[u];
            float4 wv = wo4[u];
            float gi = gv.x + bv.x + yv.x + wv.x;
            float gf = gv.y + bv.y + yv.y + wv.y;
            float gg = gv.z + bv.z + yv.z + wv.z;
            float go = gv.w + bv.w + yv.w + wv.w;

            int ug = (bn >> 2) + u;
            int cidx = b * HH + ug;
            float ci = c[cidx];
            float ig = 1.f / (1.f + expf(-gi));
            float fg = 1.f / (1.f + expf(-gf));
            float og = 1.f / (1.f + expf(-go));
            float c2 = fg * ci + ig * tanhf(gg);
            float h2 = og * tanhf(c2);

            c[cidx] = c2;
            __half h2h = __float2half_rn(h2);
            h_h[cidx] = h2h;
            outh_h[((size_t)b * SS + s) * HH + ug] = h2h;
        }
    }
}

// ---------------- fp16 GEMM, 128x128 tile, 256 threads (feat) ----------------
#define SMPB 40

__global__ __launch_bounds__(256)
void gemm_f16_big(const __half* __restrict__ A, const __half* __restrict__ B,
                  float* __restrict__ C, __half* __restrict__ Ch,
                  int M, int N, int K, int ldc)
{
    __shared__ __half As[2][128][SMPB];
    __shared__ __half Bs[2][128][SMPB];

    const int tid  = threadIdx.x;
    const int bm   = blockIdx.x * 128;
    const int bn   = blockIdx.y * 128;
    const int w    = tid >> 5, lane = tid & 31;
    const int g    = lane >> 2, tg = lane & 3;
    const int wm   = (w & 1) * 64;
    const int wn   = (w >> 1) * 32;

    float acc[4][4][4];
#pragma unroll
    for (int mt = 0; mt < 4; ++mt)
#pragma unroll
        for (int nt = 0; nt < 4; ++nt)
#pragma unroll
            for (int r = 0; r < 4; ++r) acc[mt][nt][r] = 0.f;

    uint4 stA[2], stB[2];
    const uint4 z4 = make_uint4(0u, 0u, 0u, 0u);
    const int nk = K >> 5;
    const int kld = K >> 3;

    auto ldg = [&](int k0) {
#pragma unroll
        for (int i = 0; i < 2; ++i) {
            int id = tid + i * 256;
            int r = id >> 2, cg = id & 3;
            const uint4* Ar = reinterpret_cast<const uint4*>(A) + (size_t)(bm + r) * kld + (k0 >> 3) + cg;
            const uint4* Br = reinterpret_cast<const uint4*>(B) + (size_t)(bn + r) * kld + (k0 >> 3) + cg;
            stA[i] = (bm + r < M) ? *Ar : z4;
            stB[i] = (bn + r < N) ? *Br : z4;
        }
    };
    auto sts = [&](int buf) {
#pragma unroll
        for (int i = 0; i < 2; ++i) {
            int id = tid + i * 256;
            int r = id >> 2, cg = id & 3;
            *reinterpret_cast<uint4*>(&As[buf][r][cg * 8]) = stA[i];
            *reinterpret_cast<uint4*>(&Bs[buf][r][cg * 8]) = stB[i];
        }
    };

    ldg(0); sts(0);
    __syncthreads();

    for (int kt = 0; kt < nk; ++kt) {
        const int buf = kt & 1;
        if (kt + 1 < nk) ldg((kt + 1) << 5);

#pragma unroll
        for (int ks = 0; ks < 32; ks += 16) {
            unsigned a[4][4];
#pragma unroll
            for (int mt = 0; mt < 4; ++mt) {
                int r0 = wm + mt * 16 + g;
                a[mt][0] = *reinterpret_cast<const unsigned*>(&As[buf][r0][ks + 2 * tg]);
                a[mt][1] = *reinterpret_cast<const unsigned*>(&As[buf][r0 + 8][ks + 2 * tg]);
                a[mt][2] = *reinterpret_cast<const unsigned*>(&As[buf][r0][ks + 8 + 2 * tg]);
                a[mt][3] = *reinterpret_cast<const unsigned*>(&As[buf][r0 + 8][ks + 8 + 2 * tg]);
            }
            unsigned bf[4][2];
#pragma unroll
            for (int nt = 0; nt < 4; ++nt) {
                int n0 = wn + nt * 8 + g;
                bf[nt][0] = *reinterpret_cast<const unsigned*>(&Bs[buf][n0][ks + 2 * tg]);
                bf[nt][1] = *reinterpret_cast<const unsigned*>(&Bs[buf][n0][ks + 8 + 2 * tg]);
            }
#pragma unroll
            for (int mt = 0; mt < 4; ++mt)
#pragma unroll
                for (int nt = 0; nt < 4; ++nt)
                    MMA_F16(acc[mt][nt], a[mt], bf[nt]);
        }

        if (kt + 1 < nk) { __syncthreads(); sts((kt + 1) & 1); }
        __syncthreads();
    }

#pragma unroll
    for (int mt = 0; mt < 4; ++mt)
#pragma unroll
        for (int nt = 0; nt < 4; ++nt)
#pragma unroll
            for (int r = 0; r < 4; ++r) {
                int row = bm + wm + mt * 16 + g + ((r >> 1) << 3);
                int col = bn + wn + nt * 8 + 2 * tg + (r & 1);
                if (row < M && col < N) {
                    float v = acc[mt][nt][r];
                    if (Ch) Ch[(size_t)row * ldc + col] = __float2half_rn(v);
                    else    C [(size_t)row * ldc + col] = v;
                }
            }
}

// ---------------- fused attention (fp16, uint4 loads) — R6 version ----------------
__global__ __launch_bounds__(256)
void att_kernel(const uint4* __restrict__ H4, const uint4* __restrict__ F4,
                const float* __restrict__ hp, int hp_ld,
                const float* __restrict__ w_score, __half2* __restrict__ ctx)
{
    __shared__ float e_sh[TT];
    __shared__ float red_sh[2];
    __shared__ float red4[4][64][8];

    const int b = blockIdx.x;
    const int tid = threadIdx.x;
    const int warp = tid >> 5, lane = tid & 31;

    float2 hpv[8], wsv[8];
    {
        const float2* hp2 = reinterpret_cast<const float2*>(hp + (size_t)b * hp_ld);
        const float2* ws2 = reinterpret_cast<const float2*>(w_score);
#pragma unroll
        for (int j = 0; j < 2; ++j)
#pragma unroll
            for (int q = 0; q < 4; ++q) {
                int idx = 4 * (j * 32 + lane) + q;
                hpv[j * 4 + q] = hp2[idx];
                wsv[j * 4 + q] = ws2[idx];
            }
    }

    for (int t0 = warp; t0 < TT; t0 += 16) {
        const int t1 = t0 + 8;
        const uint4* f0 = F4 + ((size_t)b * TT + t0) * 64;
        const uint4* f1 = F4 + ((size_t)b * TT + t1) * 64;
        uint4 u0a = f0[lane], u0b = f0[32 + lane];
        uint4 u1a = f1[lane], u1b = f1[32 + lane];
        float acc0 = 0.f, acc1 = 0.f;
#pragma unroll
        for (int q = 0; q < 4; ++q) {
            {
                float2 f = __half22float2(reinterpret_cast<const __half2*>(&u0a)[q]);
                float2 hv = hpv[q], wv = wsv[q];
                float a0, a1;
                asm("tanh.approx.f32 %0, %1;" : "=f"(a0) : "f"(f.x + hv.x));
                asm("tanh.approx.f32 %0, %1;" : "=f"(a1) : "f"(f.y + hv.y));
                acc0 = fmaf(a0, wv.x, fmaf(a1, wv.y, acc0));
            }
            {
                float2 f = __half22float2(reinterpret_cast<const __half2*>(&u0b)[q]);
                float2 hv = hpv[4 + q], wv = wsv[4 + q];
                float a0, a1;
                asm("tanh.approx.f32 %0, %1;" : "=f"(a0) : "f"(f.x + hv.x));
                asm("tanh.approx.f32 %0, %1;" : "=f"(a1) : "f"(f.y + hv.y));
                acc0 = fmaf(a0, wv.x, fmaf(a1, wv.y, acc0));
            }
            {
                float2 f = __half22float2(reinterpret_cast<const __half2*>(&u1a)[q]);
                float2 hv = hpv[q], wv = wsv[q];
                float a0, a1;
                asm("tanh.approx.f32 %0, %1;" : "=f"(a0) : "f"(f.x + hv.x));
                asm("tanh.approx.f32 %0, %1;" : "=f"(a1) : "f"(f.y + hv.y));
                acc1 = fmaf(a0, wv.x, fmaf(a1, wv.y, acc1));
            }
            {
                float2 f = __half22float2(reinterpret_cast<const __half2*>(&u1b)[q]);
                float2 hv = hpv[4 + q], wv = wsv[4 + q];
                float a0, a1;
                asm("tanh.approx.f32 %0, %1;" : "=f"(a0) : "f"(f.x + hv.x));
                asm("tanh.approx.f32 %0, %1;" : "=f"(a1) : "f"(f.y + hv.y));
                acc1 = fmaf(a0, wv.x, fmaf(a1, wv.y, acc1));
            }
        }
#pragma unroll
        for (int o = 16; o > 0; o >>= 1) {
            acc0 += __shfl_xor_sync(0xffffffffu, acc0, o);
            acc1 += __shfl_xor_sync(0xffffffffu, acc1, o);
        }
        if (lane == 0) { e_sh[t0] = acc0; e_sh[t1] = acc1; }
    }
    __syncthreads();

    if (tid < 32) {
        float m = fmaxf(fmaxf(e_sh[tid], e_sh[tid + 32]),
                        fmaxf(e_sh[tid + 64], e_sh[tid + 96]));
#pragma unroll
        for (int o = 16; o > 0; o >>= 1) m = fmaxf(m, __shfl_xor_sync(0xffffffffu, m, o));
        if (tid == 0) red_sh[0] = m;
    }
    __syncthreads();
    const float mx = red_sh[0];
    if (tid < TT) e_sh[tid] = __expf(e_sh[tid] - mx);
    __syncthreads();
    if (tid < 32) {
        float ssum = e_sh[tid] + e_sh[tid + 32] + e_sh[tid + 64] + e_sh[tid + 96];
#pragma unroll
        for (int o = 16; o > 0; o >>= 1) ssum += __shfl_xor_sync(0xffffffffu, ssum, o);
        if (tid == 0) red_sh[1] = 1.f / ssum;
    }
    __syncthreads();

    {
        const int tg4 = tid >> 6, ti = tid & 63;
        const uint4* Hb = H4 + (size_t)b * TT * 64 + ti;
        float acc[8];
#pragma unroll
        for (int q = 0; q < 8; ++q) acc[q] = 0.f;
        const int tbeg = tg4 * 32;
#pragma unroll 4
        for (int t = tbeg; t < tbeg + 32; ++t) {
            uint4 u = Hb[(size_t)t * 64];
            float a = e_sh[t];
#pragma unroll
            for (int q = 0; q < 4; ++q) {
                float2 v = __half22float2(reinterpret_cast<const __half2*>(&u)[q]);
                acc[2 * q]     = fmaf(a, v.x, acc[2 * q]);
                acc[2 * q + 1] = fmaf(a, v.y, acc[2 * q + 1]);
            }
        }
#pragma unroll
        for (int q = 0; q < 8; ++q) red4[tg4][ti][q] = acc[q];
    }
    __syncthreads();

    if (tid < 64) {
        const float inv = red_sh[1];
        __half2 o4[4];
#pragma unroll
        for (int q = 0; q < 4; ++q) {
            float x = (red4[0][tid][2*q]   + red4[1][tid][2*q] +
                       red4[2][tid][2*q]   + red4[3][tid][2*q]) * inv;
            float y = (red4[0][tid][2*q+1] + red4[1][tid][2*q+1] +
                       red4[2][tid][2*q+1] + red4[3][tid][2*q+1]) * inv;
            o4[q] = __float22half2_rn(make_float2(x, y));
        }
        *reinterpret_cast<uint4*>(&ctx[(size_t)b * (II / 2) + tid * 4]) =
            *reinterpret_cast<const uint4*>(o4);
    }
}

// ---------------- host launcher ----------------
extern "C" void kernel_launch(void* const* d_in, const int* in_sizes, int n_in,
                              void* d_out, int out_size)
{
    const float* batch_H = (const float*)d_in[0];
    const int*   text    = (const int*)  d_in[1];
    const float* W_feat  = (const float*)d_in[2];
    const float* W_hid   = (const float*)d_in[3];
    const float* b_hid   = (const float*)d_in[4];
    const float* w_score = (const float*)d_in[5];
    const float* W_ih    = (const float*)d_in[6];
    const float* W_hh    = (const float*)d_in[7];
    const float* b_ih    = (const float*)d_in[8];
    const float* b_hh    = (const float*)d_in[9];
    const float* W_gen   = (const float*)d_in[10];
    const float* b_gen   = (const float*)d_in[11];
    float* out = (float*)d_out;

    float *c, *Y, *WohT, *bg, *bcomb;
    __half2 *feat_h, *H_h, *ctx_h;
    __half *h_h, *outh_h, *Wx_h, *Wcomb_h, *Wfeat_h, *Wgen_h;
    cudaGetSymbolAddress((void**)&feat_h,  g_feat_h);
    cudaGetSymbolAddress((void**)&H_h,     g_H_h);
    cudaGetSymbolAddress((void**)&h_h,     g_h_h);
    cudaGetSymbolAddress((void**)&c,       g_c);
    cudaGetSymbolAddress((void**)&Y,       g_Y);
    cudaGetSymbolAddress((void**)&ctx_h,   g_ctx_h);
    cudaGetSymbolAddress((void**)&outh_h,  g_outh_h);
    cudaGetSymbolAddress((void**)&Wx_h,    g_Wx_h);
    cudaGetSymbolAddress((void**)&Wcomb_h, g_Wcomb_h);
    cudaGetSymbolAddress((void**)&Wfeat_h, g_Wfeat_h);
    cudaGetSymbolAddress((void**)&Wgen_h,  g_Wgen_h);
    cudaGetSymbolAddress((void**)&bcomb,   g_bcomb);
    cudaGetSymbolAddress((void**)&WohT,    g_WohT);
    cudaGetSymbolAddress((void**)&bg,      g_bg);

    // pack weights (fp16, gate-interleaved) + fp16 batch_H + zero state
    pack_kernel<<<512, 256>>>(W_ih, b_ih, b_hh, W_hid, W_hh, b_hid,
                              W_feat, W_gen, batch_H);

    // feat[BT, H] = batch_H @ W_feat^T  -> fp16
    gemm_f16_big<<<dim3((BB * TT) / 128, HH / 128), 256>>>(
        (const __half*)H_h, Wfeat_h, nullptr, (__half*)feat_h,
        BB * TT, HH, II, HH);

    for (int s = 0; s < SS; ++s) {
        // Y = h @ [W_hid ; W_hh_il]^T + [b_hid ; 0]   -> [B, 2560] fp32
        gemm_f16_sk<<<dim3(BB / 64, NCOMB / 64), 256>>>(
            h_h, Wcomb_h, bcomb, Y, nullptr, BB, NCOMB, HH, NCOMB);

        // fused attention (hp = Y[:, :512]) -> fp16 ctx
        att_kernel<<<BB, 256>>>((const uint4*)H_h, (const uint4*)feat_h,
                                Y, NCOMB, w_score, ctx_h);

        // gates GEMM + fused LSTM cell
        gemm_gates_sk<<<dim3(BB / 64, G4H / 64), 256>>>(
            (const __half*)ctx_h, Wx_h, bg, Y, WohT, text, s, c, h_h, outh_h);
    }

    // probs[B*S, C] = outh @ W_gen^T + b_gen
    gemm_f16_sk<<<dim3((BB * SS) / 64, (CC + 63) / 64), 256>>>(
        outh_h, Wgen_h, b_gen, out, nullptr, BB * SS, CC, HH, CC);
}

// round 13
// speedup vs baseline: 1.1716x; 1.0807x over previous
#include <cuda_runtime.h>
#include <cuda_bf16.h>
#include <cuda_fp16.h>
#include <cstdint>

// Problem constants
#define BB 512
#define TT 128
#define II 512
#define HH 512
#define CC 97
#define SS 26
#define G4H 2048           // 4*H
#define NCOMB 2560         // H + 4H
#define WIH_LD 609         // I + C

// Interleaved gate index: m = 4*u + g  <->  original row g*512 + u

// ---------------- device scratch (static, no allocs) ----------------
__device__ __half2 g_feat_h[(size_t)BB * TT * HH / 2];   // 64 MB fp16 feat
__device__ __half2 g_H_h[(size_t)BB * TT * II / 2];      // 64 MB fp16 batch_H
__device__ __half  g_h_h[BB * HH];                       // fp16 hidden state
__device__ float   g_c[BB * HH];
__device__ float   g_Y[BB * NCOMB];                      // [hp | h@Whh_il^T] fp32
__device__ __half2 g_ctx_h[BB * II / 2];                 // fp16 context
__device__ __half  g_outh_h[(size_t)BB * SS * HH];       // fp16 step outputs
__device__ __half  g_Wx_h[G4H * II];                     // W_ih[:, :I], gate-interleaved
__device__ __half  g_Wcomb_h[NCOMB * HH];                // [W_hid ; W_hh interleaved]
__device__ __half  g_Wfeat_h[HH * II];
__device__ __half  g_Wgen_h[CC * HH];
__device__ float   g_bcomb[NCOMB];                       // [b_hid ; 0]
__device__ float   g_WohT[CC * G4H];                     // W_ih[:, I:]^T interleaved
__device__ float   g_bg[G4H];                            // (b_ih + b_hh) interleaved

// ---------------- pack / init kernel ----------------
__global__ void pack_kernel(const float* __restrict__ W_ih,
                            const float* __restrict__ b_ih,
                            const float* __restrict__ b_hh,
                            const float* __restrict__ W_hid,
                            const float* __restrict__ W_hh,
                            const float* __restrict__ b_hid,
                            const float* __restrict__ W_feat,
                            const float* __restrict__ W_gen,
                            const float* __restrict__ batch_H)
{
    const int stride = gridDim.x * blockDim.x;
    const int t0 = blockIdx.x * blockDim.x + threadIdx.x;
    for (int i = t0; i < G4H * II; i += stride) {
        int n = i >> 9, k = i & 511;
        int u = n >> 2, g = n & 3;
        g_Wx_h[i] = __float2half_rn(W_ih[(g * 512 + u) * WIH_LD + k]);
    }
    for (int i = t0; i < NCOMB * HH; i += stride) {
        int n = i >> 9, k = i & 511;
        float v;
        if (n < HH) v = W_hid[n * HH + k];
        else {
            int m = n - HH, u = m >> 2, g = m & 3;
            v = W_hh[(g * 512 + u) * HH + k];
        }
        g_Wcomb_h[i] = __float2half_rn(v);
    }
    for (int i = t0; i < HH * II; i += stride)
        g_Wfeat_h[i] = __float2half_rn(W_feat[i]);
    for (int i = t0; i < CC * HH; i += stride)
        g_Wgen_h[i] = __float2half_rn(W_gen[i]);
    for (int i = t0; i < CC * G4H; i += stride) {
        int cls = i >> 11, m = i & 2047;
        int u = m >> 2, g = m & 3;
        g_WohT[i] = W_ih[(g * 512 + u) * WIH_LD + II + cls];
    }
    for (int i = t0; i < G4H; i += stride) {
        int u = i >> 2, g = i & 3;
        g_bg[i] = b_ih[g * 512 + u] + b_hh[g * 512 + u];
    }
    for (int i = t0; i < NCOMB; i += stride) g_bcomb[i] = (i < HH) ? b_hid[i] : 0.f;
    for (int i = t0; i < BB * HH; i += stride) {
        g_h_h[i] = __float2half_rn(0.f);
        g_c[i] = 0.f;
    }
    const size_t nh2 = (size_t)BB * TT * II / 2;
    const float2* src = reinterpret_cast<const float2*>(batch_H);
    for (size_t i = t0; i < nh2; i += stride)
        g_H_h[i] = __float22half2_rn(src[i]);
}

#define MMA_F16(d, a, b)                                                         \
    asm volatile("mma.sync.aligned.m16n8k16.row.col.f32.f16.f16.f32 "            \
                 "{%0,%1,%2,%3}, {%4,%5,%6,%7}, {%8,%9}, {%0,%1,%2,%3};"         \
                 : "+f"(d[0]), "+f"(d[1]), "+f"(d[2]), "+f"(d[3])                \
                 : "r"(a[0]), "r"(a[1]), "r"(a[2]), "r"(a[3]),                   \
                   "r"(b[0]), "r"(b[1]))

#define SMP 56
#define NSTAGE 3
#define STG_BYTES (64 * SMP * (int)sizeof(__half))   // 7168 per matrix per stage

__device__ __forceinline__ void cp_async16(uint32_t dst, const void* src, int srcsize) {
    asm volatile("cp.async.cg.shared.global [%0], [%1], 16, %2;\n"
                 :: "r"(dst), "l"(src), "r"(srcsize) : "memory");
}
__device__ __forceinline__ void cp_commit() {
    asm volatile("cp.async.commit_group;\n" ::: "memory");
}

// ---------------- 3-stage cp.async split-K fp16 GEMM, 64x64 tile, 256 threads ----
// 8 warps: 2x2 warp tiles x 2 K-groups; smem reduction (aliased over stage bufs).
__global__ __launch_bounds__(256)
void gemm_f16_sk(const __half* __restrict__ A, const __half* __restrict__ B,
                 const float* __restrict__ bias, float* __restrict__ C,
                 __half* __restrict__ Ch,
                 int M, int N, int K, int ldc)
{
    __shared__ __align__(16) char sraw[NSTAGE * 2 * STG_BYTES];
    __half (*As)[64][SMP] = reinterpret_cast<__half(*)[64][SMP]>(sraw);
    __half (*Bs)[64][SMP] = reinterpret_cast<__half(*)[64][SMP]>(sraw + NSTAGE * STG_BYTES);

    const int tid  = threadIdx.x;
    const int bm   = blockIdx.x * 64;
    const int bn   = blockIdx.y * 64;
    const int w    = tid >> 5, lane = tid & 31;
    const int g    = lane >> 2, tg = lane & 3;
    const int kg   = w >> 2;
    const int ws   = w & 3;
    const int wm   = (ws & 1) * 32;
    const int wn   = (ws >> 1) * 32;
    const int ks   = kg << 4;

    float acc[2][4][4];
#pragma unroll
    for (int mt = 0; mt < 2; ++mt)
#pragma unroll
        for (int nt = 0; nt < 4; ++nt)
#pragma unroll
            for (int r = 0; r < 4; ++r) acc[mt][nt][r] = 0.f;

    const int nk = K >> 5;
    const int lr = tid >> 2, lc = (tid & 3) * 8;        // half offsets
    const int arow = bm + lr, brow = bn + lr;
    const __half* aptr = A + (size_t)(arow < M ? arow : M - 1) * K + lc;
    const __half* bptr = B + (size_t)(brow < N ? brow : N - 1) * K + lc;
    const int asz = (arow < M) ? 16 : 0;
    const int bsz = (brow < N) ? 16 : 0;
    const uint32_t adst0 = (uint32_t)__cvta_generic_to_shared(&As[0][lr][lc]);
    const uint32_t bdst0 = (uint32_t)__cvta_generic_to_shared(&Bs[0][lr][lc]);

    // prologue: stages 0,1
#pragma unroll
    for (int p = 0; p < 2; ++p) {
        cp_async16(adst0 + p * STG_BYTES, aptr + p * 32, asz);
        cp_async16(bdst0 + p * STG_BYTES, bptr + p * 32, bsz);
        cp_commit();
    }

    for (int kt = 0; kt < nk; ++kt) {
        if (kt + 1 < nk) asm volatile("cp.async.wait_group 1;\n" ::: "memory");
        else             asm volatile("cp.async.wait_group 0;\n" ::: "memory");
        __syncthreads();

        if (kt + 2 < nk) {
            int st = (kt + 2) % NSTAGE;
            cp_async16(adst0 + st * STG_BYTES, aptr + (kt + 2) * 32, asz);
            cp_async16(bdst0 + st * STG_BYTES, bptr + (kt + 2) * 32, bsz);
            cp_commit();
        }

        const int buf = kt % NSTAGE;
        unsigned a[2][4];
#pragma unroll
        for (int mt = 0; mt < 2; ++mt) {
            int r0 = wm + mt * 16 + g;
            a[mt][0] = *reinterpret_cast<const unsigned*>(&As[buf][r0][ks + 2 * tg]);
            a[mt][1] = *reinterpret_cast<const unsigned*>(&As[buf][r0 + 8][ks + 2 * tg]);
            a[mt][2] = *reinterpret_cast<const unsigned*>(&As[buf][r0][ks + 8 + 2 * tg]);
            a[mt][3] = *reinterpret_cast<const unsigned*>(&As[buf][r0 + 8][ks + 8 + 2 * tg]);
        }
        unsigned bf[4][2];
#pragma unroll
        for (int nt = 0; nt < 4; ++nt) {
            int n0 = wn + nt * 8 + g;
            bf[nt][0] = *reinterpret_cast<const unsigned*>(&Bs[buf][n0][ks + 2 * tg]);
            bf[nt][1] = *reinterpret_cast<const unsigned*>(&Bs[buf][n0][ks + 8 + 2 * tg]);
        }
#pragma unroll
        for (int mt = 0; mt < 2; ++mt)
#pragma unroll
            for (int nt = 0; nt < 4; ++nt)
                MMA_F16(acc[mt][nt], a[mt], bf[nt]);
    }

    // reduction buffer aliases the As stage region (all MMAs done after barrier)
    __syncthreads();
    float (*red)[65] = reinterpret_cast<float(*)[65]>(sraw);

    if (kg == 1) {
#pragma unroll
        for (int mt = 0; mt < 2; ++mt)
#pragma unroll
            for (int nt = 0; nt < 4; ++nt)
#pragma unroll
                for (int r = 0; r < 4; ++r) {
                    int row = wm + mt * 16 + g + ((r >> 1) << 3);
                    int col = wn + nt * 8 + 2 * tg + (r & 1);
                    red[row][col] = acc[mt][nt][r];
                }
    }
    __syncthreads();
    if (kg == 0) {
#pragma unroll
        for (int mt = 0; mt < 2; ++mt)
#pragma unroll
            for (int nt = 0; nt < 4; ++nt)
#pragma unroll
                for (int r = 0; r < 4; ++r) {
                    int rl = wm + mt * 16 + g + ((r >> 1) << 3);
                    int cl = wn + nt * 8 + 2 * tg + (r & 1);
                    int row = bm + rl, col = bn + cl;
                    if (row < M && col < N) {
                        float v = acc[mt][nt][r] + red[rl][cl];
                        if (bias) v += bias[col];
                        if (Ch) Ch[(size_t)row * ldc + col] = __float2half_rn(v);
                        else    C [(size_t)row * ldc + col] = v;
                    }
                }
    }
}

// ---------------- 3-stage cp.async split-K gates GEMM + fused LSTM ----------------
__global__ __launch_bounds__(256)
void gemm_gates_sk(const __half* __restrict__ A, const __half* __restrict__ B,
                   const float* __restrict__ bg, const float* __restrict__ Y,
                   const float* __restrict__ WohT, const int* __restrict__ text, int s,
                   float* __restrict__ c, __half* __restrict__ h_h,
                   __half* __restrict__ outh_h)
{
    __shared__ __align__(16) char sraw[NSTAGE * 2 * STG_BYTES];
    __half (*As)[64][SMP] = reinterpret_cast<__half(*)[64][SMP]>(sraw);
    __half (*Bs)[64][SMP] = reinterpret_cast<__half(*)[64][SMP]>(sraw + NSTAGE * STG_BYTES);

    const int tid  = threadIdx.x;
    const int bm   = blockIdx.x * 64;
    const int bn   = blockIdx.y * 64;
    const int w    = tid >> 5, lane = tid & 31;
    const int g    = lane >> 2, tg = lane & 3;
    const int kg   = w >> 2;
    const int ws   = w & 3;
    const int wm   = (ws & 1) * 32;
    const int wn   = (ws >> 1) * 32;
    const int ks   = kg << 4;

    float acc[2][4][4];
#pragma unroll
    for (int mt = 0; mt < 2; ++mt)
#pragma unroll
        for (int nt = 0; nt < 4; ++nt)
#pragma unroll
            for (int r = 0; r < 4; ++r) acc[mt][nt][r] = 0.f;

    const int nk = II >> 5;
    const int lr = tid >> 2, lc = (tid & 3) * 8;
    const __half* aptr = A + (size_t)(bm + lr) * II + lc;
    const __half* bptr = B + (size_t)(bn + lr) * II + lc;
    const uint32_t adst0 = (uint32_t)__cvta_generic_to_shared(&As[0][lr][lc]);
    const uint32_t bdst0 = (uint32_t)__cvta_generic_to_shared(&Bs[0][lr][lc]);

#pragma unroll
    for (int p = 0; p < 2; ++p) {
        cp_async16(adst0 + p * STG_BYTES, aptr + p * 32, 16);
        cp_async16(bdst0 + p * STG_BYTES, bptr + p * 32, 16);
        cp_commit();
    }

    for (int kt = 0; kt < nk; ++kt) {
        if (kt + 1 < nk) asm volatile("cp.async.wait_group 1;\n" ::: "memory");
        else             asm volatile("cp.async.wait_group 0;\n" ::: "memory");
        __syncthreads();

        if (kt + 2 < nk) {
            int st = (kt + 2) % NSTAGE;
            cp_async16(adst0 + st * STG_BYTES, aptr + (kt + 2) * 32, 16);
            cp_async16(bdst0 + st * STG_BYTES, bptr + (kt + 2) * 32, 16);
            cp_commit();
        }

        const int buf = kt % NSTAGE;
        unsigned a[2][4];
#pragma unroll
        for (int mt = 0; mt < 2; ++mt) {
            int r0 = wm + mt * 16 + g;
            a[mt][0] = *reinterpret_cast<const unsigned*>(&As[buf][r0][ks + 2 * tg]);
            a[mt][1] = *reinterpret_cast<const unsigned*>(&As[buf][r0 + 8][ks + 2 * tg]);
            a[mt][2] = *reinterpret_cast<const unsigned*>(&As[buf][r0][ks + 8 + 2 * tg]);
            a[mt][3] = *reinterpret_cast<const unsigned*>(&As[buf][r0 + 8][ks + 8 + 2 * tg]);
        }
        unsigned bf[4][2];
#pragma unroll
        for (int nt = 0; nt < 4; ++nt) {
            int n0 = wn + nt * 8 + g;
            bf[nt][0] = *reinterpret_cast<const unsigned*>(&Bs[buf][n0][ks + 2 * tg]);
            bf[nt][1] = *reinterpret_cast<const unsigned*>(&Bs[buf][n0][ks + 8 + 2 * tg]);
        }
#pragma unroll
        for (int mt = 0; mt < 2; ++mt)
#pragma unroll
            for (int nt = 0; nt < 4; ++nt)
                MMA_F16(acc[mt][nt], a[mt], bf[nt]);
    }

    // gates staging buffer aliases the As stage region
    __syncthreads();
    float (*gsm)[68] = reinterpret_cast<float(*)[68]>(sraw);

    if (kg == 1) {
#pragma unroll
        for (int mt = 0; mt < 2; ++mt)
#pragma unroll
            for (int nt = 0; nt < 4; ++nt)
#pragma unroll
                for (int r = 0; r < 4; ++r) {
                    int rl = wm + mt * 16 + g + ((r >> 1) << 3);
                    int cl = wn + nt * 8 + 2 * tg + (r & 1);
                    gsm[rl][cl] = acc[mt][nt][r];
                }
    }
    __syncthreads();
    if (kg == 0) {
#pragma unroll
        for (int mt = 0; mt < 2; ++mt)
#pragma unroll
            for (int nt = 0; nt < 4; ++nt)
#pragma unroll
                for (int r = 0; r < 4; ++r) {
                    int rl = wm + mt * 16 + g + ((r >> 1) << 3);
                    int cl = wn + nt * 8 + 2 * tg + (r & 1);
                    gsm[rl][cl] += acc[mt][nt][r];
                }
    }
    __syncthreads();

    // fused LSTM: 256 threads x 4 (row, unit) items
    {
        const int r  = tid >> 2;            // local row 0..63
        const int u0 = tid & 3;
        const int b  = bm + r;
        const int cls = text[b * SS + s];
        const float4* wo4 = reinterpret_cast<const float4*>(WohT + (size_t)cls * G4H + bn);
        const float4* bg4 = reinterpret_cast<const float4*>(bg + bn);
        const float4* Y4  = reinterpret_cast<const float4*>(Y + (size_t)b * NCOMB + HH + bn);
#pragma unroll
        for (int j = 0; j < 4; ++j) {
            int u = 4 * j + u0;             // 0..15
            float4 gv = *reinterpret_cast<const float4*>(&gsm[r][4 * u]);
            float4 bv = bg4[u];
            float4 yv = Y4[u];
            float4 wv = wo4[u];
            float gi = gv.x + bv.x + yv.x + wv.x;
            float gf = gv.y + bv.y + yv.y + wv.y;
            float gg = gv.z + bv.z + yv.z + wv.z;
            float go = gv.w + bv.w + yv.w + wv.w;

            int ug = (bn >> 2) + u;
            int cidx = b * HH + ug;
            float ci = c[cidx];
            float ig = 1.f / (1.f + expf(-gi));
            float fg = 1.f / (1.f + expf(-gf));
            float og = 1.f / (1.f + expf(-go));
            float c2 = fg * ci + ig * tanhf(gg);
            float h2 = og * tanhf(c2);

            c[cidx] = c2;
            __half h2h = __float2half_rn(h2);
            h_h[cidx] = h2h;
            outh_h[((size_t)b * SS + s) * HH + ug] = h2h;
        }
    }
}

// ---------------- fp16 GEMM, 128x128 tile, 256 threads (feat) ----------------
#define SMPB 40

__global__ __launch_bounds__(256)
void gemm_f16_big(const __half* __restrict__ A, const __half* __restrict__ B,
                  float* __restrict__ C, __half* __restrict__ Ch,
                  int M, int N, int K, int ldc)
{
    __shared__ __half As[2][128][SMPB];
    __shared__ __half Bs[2][128][SMPB];

    const int tid  = threadIdx.x;
    const int bm   = blockIdx.x * 128;
    const int bn   = blockIdx.y * 128;
    const int w    = tid >> 5, lane = tid & 31;
    const int g    = lane >> 2, tg = lane & 3;
    const int wm   = (w & 1) * 64;
    const int wn   = (w >> 1) * 32;

    float acc[4][4][4];
#pragma unroll
    for (int mt = 0; mt < 4; ++mt)
#pragma unroll
        for (int nt = 0; nt < 4; ++nt)
#pragma unroll
            for (int r = 0; r < 4; ++r) acc[mt][nt][r] = 0.f;

    uint4 stA[2], stB[2];
    const uint4 z4 = make_uint4(0u, 0u, 0u, 0u);
    const int nk = K >> 5;
    const int kld = K >> 3;

    auto ldg = [&](int k0) {
#pragma unroll
        for (int i = 0; i < 2; ++i) {
            int id = tid + i * 256;
            int r = id >> 2, cg = id & 3;
            const uint4* Ar = reinterpret_cast<const uint4*>(A) + (size_t)(bm + r) * kld + (k0 >> 3) + cg;
            const uint4* Br = reinterpret_cast<const uint4*>(B) + (size_t)(bn + r) * kld + (k0 >> 3) + cg;
            stA[i] = (bm + r < M) ? *Ar : z4;
            stB[i] = (bn + r < N) ? *Br : z4;
        }
    };
    auto sts = [&](int buf) {
#pragma unroll
        for (int i = 0; i < 2; ++i) {
            int id = tid + i * 256;
            int r = id >> 2, cg = id & 3;
            *reinterpret_cast<uint4*>(&As[buf][r][cg * 8]) = stA[i];
            *reinterpret_cast<uint4*>(&Bs[buf][r][cg * 8]) = stB[i];
        }
    };

    ldg(0); sts(0);
    __syncthreads();

    for (int kt = 0; kt < nk; ++kt) {
        const int buf = kt & 1;
        if (kt + 1 < nk) ldg((kt + 1) << 5);

#pragma unroll
        for (int ks = 0; ks < 32; ks += 16) {
            unsigned a[4][4];
#pragma unroll
            for (int mt = 0; mt < 4; ++mt) {
                int r0 = wm + mt * 16 + g;
                a[mt][0] = *reinterpret_cast<const unsigned*>(&As[buf][r0][ks + 2 * tg]);
                a[mt][1] = *reinterpret_cast<const unsigned*>(&As[buf][r0 + 8][ks + 2 * tg]);
                a[mt][2] = *reinterpret_cast<const unsigned*>(&As[buf][r0][ks + 8 + 2 * tg]);
                a[mt][3] = *reinterpret_cast<const unsigned*>(&As[buf][r0 + 8][ks + 8 + 2 * tg]);
            }
            unsigned bf[4][2];
#pragma unroll
            for (int nt = 0; nt < 4; ++nt) {
                int n0 = wn + nt * 8 + g;
                bf[nt][0] = *reinterpret_cast<const unsigned*>(&Bs[buf][n0][ks + 2 * tg]);
                bf[nt][1] = *reinterpret_cast<const unsigned*>(&Bs[buf][n0][ks + 8 + 2 * tg]);
            }
#pragma unroll
            for (int mt = 0; mt < 4; ++mt)
#pragma unroll
                for (int nt = 0; nt < 4; ++nt)
                    MMA_F16(acc[mt][nt], a[mt], bf[nt]);
        }

        if (kt + 1 < nk) { __syncthreads(); sts((kt + 1) & 1); }
        __syncthreads();
    }

#pragma unroll
    for (int mt = 0; mt < 4; ++mt)
#pragma unroll
        for (int nt = 0; nt < 4; ++nt)
#pragma unroll
            for (int r = 0; r < 4; ++r) {
                int row = bm + wm + mt * 16 + g + ((r >> 1) << 3);
                int col = bn + wn + nt * 8 + 2 * tg + (r & 1);
                if (row < M && col < N) {
                    float v = acc[mt][nt][r];
                    if (Ch) Ch[(size_t)row * ldc + col] = __float2half_rn(v);
                    else    C [(size_t)row * ldc + col] = v;
                }
            }
}

// ---------------- fused attention (fp16, uint4 loads) ----------------
__global__ __launch_bounds__(256)
void att_kernel(const uint4* __restrict__ H4, const uint4* __restrict__ F4,
                const float* __restrict__ hp, int hp_ld,
                const float* __restrict__ w_score, __half2* __restrict__ ctx)
{
    __shared__ float e_sh[TT];
    __shared__ float red_sh[2];
    __shared__ float red4[4][64][8];

    const int b = blockIdx.x;
    const int tid = threadIdx.x;
    const int warp = tid >> 5, lane = tid & 31;

    float2 hpv[8], wsv[8];
    {
        const float2* hp2 = reinterpret_cast<const float2*>(hp + (size_t)b * hp_ld);
        const float2* ws2 = reinterpret_cast<const float2*>(w_score);
#pragma unroll
        for (int j = 0; j < 2; ++j)
#pragma unroll
            for (int q = 0; q < 4; ++q) {
                int idx = 4 * (j * 32 + lane) + q;
                hpv[j * 4 + q] = hp2[idx];
                wsv[j * 4 + q] = ws2[idx];
            }
    }

    for (int t0 = warp; t0 < TT; t0 += 16) {
        const int t1 = t0 + 8;
        const uint4* f0 = F4 + ((size_t)b * TT + t0) * 64;
        const uint4* f1 = F4 + ((size_t)b * TT + t1) * 64;
        uint4 u0a = f0[lane], u0b = f0[32 + lane];
        uint4 u1a = f1[lane], u1b = f1[32 + lane];
        float acc0 = 0.f, acc1 = 0.f;
#pragma unroll
        for (int q = 0; q < 4; ++q) {
            {
                float2 f = __half22float2(reinterpret_cast<const __half2*>(&u0a)[q]);
                float2 hv = hpv[q], wv = wsv[q];
                float a0, a1;
                asm("tanh.approx.f32 %0, %1;" : "=f"(a0) : "f"(f.x + hv.x));
                asm("tanh.approx.f32 %0, %1;" : "=f"(a1) : "f"(f.y + hv.y));
                acc0 = fmaf(a0, wv.x, fmaf(a1, wv.y, acc0));
            }
            {
                float2 f = __half22float2(reinterpret_cast<const __half2*>(&u0b)[q]);
                float2 hv = hpv[4 + q], wv = wsv[4 + q];
                float a0, a1;
                asm("tanh.approx.f32 %0, %1;" : "=f"(a0) : "f"(f.x + hv.x));
                asm("tanh.approx.f32 %0, %1;" : "=f"(a1) : "f"(f.y + hv.y));
                acc0 = fmaf(a0, wv.x, fmaf(a1, wv.y, acc0));
            }
            {
                float2 f = __half22float2(reinterpret_cast<const __half2*>(&u1a)[q]);
                float2 hv = hpv[q], wv = wsv[q];
                float a0, a1;
                asm("tanh.approx.f32 %0, %1;" : "=f"(a0) : "f"(f.x + hv.x));
                asm("tanh.approx.f32 %0, %1;" : "=f"(a1) : "f"(f.y + hv.y));
                acc1 = fmaf(a0, wv.x, fmaf(a1, wv.y, acc1));
            }
            {
                float2 f = __half22float2(reinterpret_cast<const __half2*>(&u1b)[q]);
                float2 hv = hpv[4 + q], wv = wsv[4 + q];
                float a0, a1;
                asm("tanh.approx.f32 %0, %1;" : "=f"(a0) : "f"(f.x + hv.x));
                asm("tanh.approx.f32 %0, %1;" : "=f"(a1) : "f"(f.y + hv.y));
                acc1 = fmaf(a0, wv.x, fmaf(a1, wv.y, acc1));
            }
        }
#pragma unroll
        for (int o = 16; o > 0; o >>= 1) {
            acc0 += __shfl_xor_sync(0xffffffffu, acc0, o);
            acc1 += __shfl_xor_sync(0xffffffffu, acc1, o);
        }
        if (lane == 0) { e_sh[t0] = acc0; e_sh[t1] = acc1; }
    }
    __syncthreads();

    if (tid < 32) {
        float m = fmaxf(fmaxf(e_sh[tid], e_sh[tid + 32]),
                        fmaxf(e_sh[tid + 64], e_sh[tid + 96]));
#pragma unroll
        for (int o = 16; o > 0; o >>= 1) m = fmaxf(m, __shfl_xor_sync(0xffffffffu, m, o));
        if (tid == 0) red_sh[0] = m;
    }
    __syncthreads();
    const float mx = red_sh[0];
    if (tid < TT) e_sh[tid] = __expf(e_sh[tid] - mx);
    __syncthreads();
    if (tid < 32) {
        float ssum = e_sh[tid] + e_sh[tid + 32] + e_sh[tid + 64] + e_sh[tid + 96];
#pragma unroll
        for (int o = 16; o > 0; o >>= 1) ssum += __shfl_xor_sync(0xffffffffu, ssum, o);
        if (tid == 0) red_sh[1] = 1.f / ssum;
    }
    __syncthreads();

    {
        const int tg4 = tid >> 6, ti = tid & 63;
        const uint4* Hb = H4 + (size_t)b * TT * 64 + ti;
        float acc[8];
#pragma unroll
        for (int q = 0; q < 8; ++q) acc[q] = 0.f;
        const int tbeg = tg4 * 32;
#pragma unroll 4
        for (int t = tbeg; t < tbeg + 32; ++t) {
            uint4 u = Hb[(size_t)t * 64];
            float a = e_sh[t];
#pragma unroll
            for (int q = 0; q < 4; ++q) {
                float2 v = __half22float2(reinterpret_cast<const __half2*>(&u)[q]);
                acc[2 * q]     = fmaf(a, v.x, acc[2 * q]);
                acc[2 * q + 1] = fmaf(a, v.y, acc[2 * q + 1]);
            }
        }
#pragma unroll
        for (int q = 0; q < 8; ++q) red4[tg4][ti][q] = acc[q];
    }
    __syncthreads();

    if (tid < 64) {
        const float inv = red_sh[1];
        __half2 o4[4];
#pragma unroll
        for (int q = 0; q < 4; ++q) {
            float x = (red4[0][tid][2*q]   + red4[1][tid][2*q] +
                       red4[2][tid][2*q]   + red4[3][tid][2*q]) * inv;
            float y = (red4[0][tid][2*q+1] + red4[1][tid][2*q+1] +
                       red4[2][tid][2*q+1] + red4[3][tid][2*q+1]) * inv;
            o4[q] = __float22half2_rn(make_float2(x, y));
        }
        *reinterpret_cast<uint4*>(&ctx[(size_t)b * (II / 2) + tid * 4]) =
            *reinterpret_cast<const uint4*>(o4);
    }
}

// ---------------- host launcher ----------------
extern "C" void kernel_launch(void* const* d_in, const int* in_sizes, int n_in,
                              void* d_out, int out_size)
{
    const float* batch_H = (const float*)d_in[0];
    const int*   text    = (const int*)  d_in[1];
    const float* W_feat  = (const float*)d_in[2];
    const float* W_hid   = (const float*)d_in[3];
    const float* b_hid   = (const float*)d_in[4];
    const float* w_score = (const float*)d_in[5];
    const float* W_ih    = (const float*)d_in[6];
    const float* W_hh    = (const float*)d_in[7];
    const float* b_ih    = (const float*)d_in[8];
    const float* b_hh    = (const float*)d_in[9];
    const float* W_gen   = (const float*)d_in[10];
    const float* b_gen   = (const float*)d_in[11];
    float* out = (float*)d_out;

    float *c, *Y, *WohT, *bg, *bcomb;
    __half2 *feat_h, *H_h, *ctx_h;
    __half *h_h, *outh_h, *Wx_h, *Wcomb_h, *Wfeat_h, *Wgen_h;
    cudaGetSymbolAddress((void**)&feat_h,  g_feat_h);
    cudaGetSymbolAddress((void**)&H_h,     g_H_h);
    cudaGetSymbolAddress((void**)&h_h,     g_h_h);
    cudaGetSymbolAddress((void**)&c,       g_c);
    cudaGetSymbolAddress((void**)&Y,       g_Y);
    cudaGetSymbolAddress((void**)&ctx_h,   g_ctx_h);
    cudaGetSymbolAddress((void**)&outh_h,  g_outh_h);
    cudaGetSymbolAddress((void**)&Wx_h,    g_Wx_h);
    cudaGetSymbolAddress((void**)&Wcomb_h, g_Wcomb_h);
    cudaGetSymbolAddress((void**)&Wfeat_h, g_Wfeat_h);
    cudaGetSymbolAddress((void**)&Wgen_h,  g_Wgen_h);
    cudaGetSymbolAddress((void**)&bcomb,   g_bcomb);
    cudaGetSymbolAddress((void**)&WohT,    g_WohT);
    cudaGetSymbolAddress((void**)&bg,      g_bg);

    // pack weights (fp16, gate-interleaved) + fp16 batch_H + zero state
    pack_kernel<<<512, 256>>>(W_ih, b_ih, b_hh, W_hid, W_hh, b_hid,
                              W_feat, W_gen, batch_H);

    // feat[BT, H] = batch_H @ W_feat^T  -> fp16
    gemm_f16_big<<<dim3((BB * TT) / 128, HH / 128), 256>>>(
        (const __half*)H_h, Wfeat_h, nullptr, (__half*)feat_h,
        BB * TT, HH, II, HH);

    for (int s = 0; s < SS; ++s) {
        // Y = h @ [W_hid ; W_hh_il]^T + [b_hid ; 0]   -> [B, 2560] fp32
        gemm_f16_sk<<<dim3(BB / 64, NCOMB / 64), 256>>>(
            h_h, Wcomb_h, bcomb, Y, nullptr, BB, NCOMB, HH, NCOMB);

        // fused attention (hp = Y[:, :512]) -> fp16 ctx
        att_kernel<<<BB, 256>>>((const uint4*)H_h, (const uint4*)feat_h,
                                Y, NCOMB, w_score, ctx_h);

        // gates GEMM + fused LSTM cell
        gemm_gates_sk<<<dim3(BB / 64, G4H / 64), 256>>>(
            (const __half*)ctx_h, Wx_h, bg, Y, WohT, text, s, c, h_h, outh_h);
    }

    // probs[B*S, C] = outh @ W_gen^T + b_gen
    gemm_f16_sk<<<dim3((BB * SS) / 64, (CC + 63) / 64), 256>>>(
        outh_h, Wgen_h, b_gen, out, nullptr, BB * SS, CC, HH, CC);
}

// round 14
// speedup vs baseline: 1.1774x; 1.0049x over previous
#include <cuda_runtime.h>
#include <cuda_bf16.h>
#include <cuda_fp16.h>
#include <cstdint>

// Problem constants
#define BB 512
#define TT 128
#define II 512
#define HH 512
#define CC 97
#define SS 26
#define G4H 2048           // 4*H
#define NCOMB 2560         // H + 4H
#define WIH_LD 609         // I + C

// Interleaved gate index: m = 4*u + g  <->  original row g*512 + u

// ---------------- device scratch (static, no allocs) ----------------
__device__ __half2 g_feat_h[(size_t)BB * TT * HH / 2];   // 64 MB fp16 feat
__device__ __half2 g_H_h[(size_t)BB * TT * II / 2];      // 64 MB fp16 batch_H
__device__ __half  g_h_h[BB * HH];                       // fp16 hidden state
__device__ float   g_c[BB * HH];
__device__ float   g_Y[BB * NCOMB];                      // [hp | h@Whh_il^T] fp32
__device__ __half2 g_ctx_h[BB * II / 2];                 // fp16 context
__device__ __half  g_outh_h[(size_t)BB * SS * HH];       // fp16 step outputs
__device__ __half  g_Wx_h[G4H * II];                     // W_ih[:, :I], gate-interleaved
__device__ __half  g_Wcomb_h[NCOMB * HH];                // [W_hid ; W_hh interleaved]
__device__ __half  g_Wfeat_h[HH * II];
__device__ __half  g_Wgen_h[CC * HH];
__device__ float   g_bcomb[NCOMB];                       // [b_hid ; 0]
__device__ float   g_WohT[CC * G4H];                     // W_ih[:, I:]^T interleaved
__device__ float   g_bg[G4H];                            // (b_ih + b_hh) interleaved

// ---------------- pack / init kernel ----------------
__global__ void pack_kernel(const float* __restrict__ W_ih,
                            const float* __restrict__ b_ih,
                            const float* __restrict__ b_hh,
                            const float* __restrict__ W_hid,
                            const float* __restrict__ W_hh,
                            const float* __restrict__ b_hid,
                            const float* __restrict__ W_feat,
                            const float* __restrict__ W_gen,
                            const float* __restrict__ batch_H)
{
    const int stride = gridDim.x * blockDim.x;
    const int t0 = blockIdx.x * blockDim.x + threadIdx.x;
    for (int i = t0; i < G4H * II; i += stride) {
        int n = i >> 9, k = i & 511;
        int u = n >> 2, g = n & 3;
        g_Wx_h[i] = __float2half_rn(W_ih[(g * 512 + u) * WIH_LD + k]);
    }
    for (int i = t0; i < NCOMB * HH; i += stride) {
        int n = i >> 9, k = i & 511;
        float v;
        if (n < HH) v = W_hid[n * HH + k];
        else {
            int m = n - HH, u = m >> 2, g = m & 3;
            v = W_hh[(g * 512 + u) * HH + k];
        }
        g_Wcomb_h[i] = __float2half_rn(v);
    }
    for (int i = t0; i < HH * II; i += stride)
        g_Wfeat_h[i] = __float2half_rn(W_feat[i]);
    for (int i = t0; i < CC * HH; i += stride)
        g_Wgen_h[i] = __float2half_rn(W_gen[i]);
    for (int i = t0; i < CC * G4H; i += stride) {
        int cls = i >> 11, m = i & 2047;
        int u = m >> 2, g = m & 3;
        g_WohT[i] = W_ih[(g * 512 + u) * WIH_LD + II + cls];
    }
    for (int i = t0; i < G4H; i += stride) {
        int u = i >> 2, g = i & 3;
        g_bg[i] = b_ih[g * 512 + u] + b_hh[g * 512 + u];
    }
    for (int i = t0; i < NCOMB; i += stride) g_bcomb[i] = (i < HH) ? b_hid[i] : 0.f;
    for (int i = t0; i < BB * HH; i += stride) {
        g_h_h[i] = __float2half_rn(0.f);
        g_c[i] = 0.f;
    }
    const size_t nh2 = (size_t)BB * TT * II / 2;
    const float2* src = reinterpret_cast<const float2*>(batch_H);
    for (size_t i = t0; i < nh2; i += stride)
        g_H_h[i] = __float22half2_rn(src[i]);
}

#define MMA_F16(d, a, b)                                                         \
    asm volatile("mma.sync.aligned.m16n8k16.row.col.f32.f16.f16.f32 "            \
                 "{%0,%1,%2,%3}, {%4,%5,%6,%7}, {%8,%9}, {%0,%1,%2,%3};"         \
                 : "+f"(d[0]), "+f"(d[1]), "+f"(d[2]), "+f"(d[3])                \
                 : "r"(a[0]), "r"(a[1]), "r"(a[2]), "r"(a[3]),                   \
                   "r"(b[0]), "r"(b[1]))

#define SMP 56
#define NST 4
#define STG_BYTES (64 * SMP * (int)sizeof(__half))   // 7168 per matrix per stage
#define SMEM_SK (NST * 2 * STG_BYTES)                // 57344

__device__ __forceinline__ void cp_async16(uint32_t dst, const void* src, int srcsize) {
    asm volatile("cp.async.cg.shared.global [%0], [%1], 16, %2;\n"
                 :: "r"(dst), "l"(src), "r"(srcsize) : "memory");
}
__device__ __forceinline__ void cp_commit() {
    asm volatile("cp.async.commit_group;\n" ::: "memory");
}
__device__ __forceinline__ void cp_wait(int kt, int nk) {
    if (kt + 3 <= nk)      asm volatile("cp.async.wait_group 2;\n" ::: "memory");
    else if (kt + 2 <= nk) asm volatile("cp.async.wait_group 1;\n" ::: "memory");
    else                   asm volatile("cp.async.wait_group 0;\n" ::: "memory");
}

// fast, saturating transcendentals (abs err ~1e-7)
__device__ __forceinline__ float fsig(float x)  { return __fdividef(1.f, 1.f + __expf(-x)); }
__device__ __forceinline__ float ftanh(float x) { float e = __expf(2.f * x); return 1.f - __fdividef(2.f, e + 1.f); }

// ---------------- 4-stage cp.async split-K fp16 GEMM, 64x64 tile, 256 threads ----
// 8 warps: 2x2 warp tiles x 2 K-groups; smem reduction (aliased over stage bufs).
__global__ __launch_bounds__(256)
void gemm_f16_sk(const __half* __restrict__ A, const __half* __restrict__ B,
                 const float* __restrict__ bias, float* __restrict__ C,
                 __half* __restrict__ Ch,
                 int M, int N, int K, int ldc)
{
    extern __shared__ __align__(16) char sraw[];
    __half (*As)[64][SMP] = reinterpret_cast<__half(*)[64][SMP]>(sraw);
    __half (*Bs)[64][SMP] = reinterpret_cast<__half(*)[64][SMP]>(sraw + NST * STG_BYTES);

    const int tid  = threadIdx.x;
    const int bm   = blockIdx.x * 64;
    const int bn   = blockIdx.y * 64;
    const int w    = tid >> 5, lane = tid & 31;
    const int g    = lane >> 2, tg = lane & 3;
    const int kg   = w >> 2;
    const int ws   = w & 3;
    const int wm   = (ws & 1) * 32;
    const int wn   = (ws >> 1) * 32;
    const int ks   = kg << 4;

    float acc[2][4][4];
#pragma unroll
    for (int mt = 0; mt < 2; ++mt)
#pragma unroll
        for (int nt = 0; nt < 4; ++nt)
#pragma unroll
            for (int r = 0; r < 4; ++r) acc[mt][nt][r] = 0.f;

    const int nk = K >> 5;
    const int lr = tid >> 2, lc = (tid & 3) * 8;        // half offsets
    const int arow = bm + lr, brow = bn + lr;
    const __half* aptr = A + (size_t)(arow < M ? arow : M - 1) * K + lc;
    const __half* bptr = B + (size_t)(brow < N ? brow : N - 1) * K + lc;
    const int asz = (arow < M) ? 16 : 0;
    const int bsz = (brow < N) ? 16 : 0;
    const uint32_t adst0 = (uint32_t)__cvta_generic_to_shared(&As[0][lr][lc]);
    const uint32_t bdst0 = (uint32_t)__cvta_generic_to_shared(&Bs[0][lr][lc]);

    // prologue: stages 0,1,2
#pragma unroll
    for (int p = 0; p < NST - 1; ++p) {
        cp_async16(adst0 + p * STG_BYTES, aptr + p * 32, asz);
        cp_async16(bdst0 + p * STG_BYTES, bptr + p * 32, bsz);
        cp_commit();
    }

    for (int kt = 0; kt < nk; ++kt) {
        cp_wait(kt, nk);
        __syncthreads();

        if (kt + NST - 1 < nk) {
            int st = (kt + NST - 1) % NST;
            cp_async16(adst0 + st * STG_BYTES, aptr + (kt + NST - 1) * 32, asz);
            cp_async16(bdst0 + st * STG_BYTES, bptr + (kt + NST - 1) * 32, bsz);
            cp_commit();
        }

        const int buf = kt % NST;
        unsigned a[2][4];
#pragma unroll
        for (int mt = 0; mt < 2; ++mt) {
            int r0 = wm + mt * 16 + g;
            a[mt][0] = *reinterpret_cast<const unsigned*>(&As[buf][r0][ks + 2 * tg]);
            a[mt][1] = *reinterpret_cast<const unsigned*>(&As[buf][r0 + 8][ks + 2 * tg]);
            a[mt][2] = *reinterpret_cast<const unsigned*>(&As[buf][r0][ks + 8 + 2 * tg]);
            a[mt][3] = *reinterpret_cast<const unsigned*>(&As[buf][r0 + 8][ks + 8 + 2 * tg]);
        }
        unsigned bf[4][2];
#pragma unroll
        for (int nt = 0; nt < 4; ++nt) {
            int n0 = wn + nt * 8 + g;
            bf[nt][0] = *reinterpret_cast<const unsigned*>(&Bs[buf][n0][ks + 2 * tg]);
            bf[nt][1] = *reinterpret_cast<const unsigned*>(&Bs[buf][n0][ks + 8 + 2 * tg]);
        }
#pragma unroll
        for (int mt = 0; mt < 2; ++mt)
#pragma unroll
            for (int nt = 0; nt < 4; ++nt)
                MMA_F16(acc[mt][nt], a[mt], bf[nt]);
    }

    // reduction buffer aliases the As stage region (all MMAs done after barrier)
    __syncthreads();
    float (*red)[65] = reinterpret_cast<float(*)[65]>(sraw);

    if (kg == 1) {
#pragma unroll
        for (int mt = 0; mt < 2; ++mt)
#pragma unroll
            for (int nt = 0; nt < 4; ++nt)
#pragma unroll
                for (int r = 0; r < 4; ++r) {
                    int row = wm + mt * 16 + g + ((r >> 1) << 3);
                    int col = wn + nt * 8 + 2 * tg + (r & 1);
                    red[row][col] = acc[mt][nt][r];
                }
    }
    __syncthreads();
    if (kg == 0) {
#pragma unroll
        for (int mt = 0; mt < 2; ++mt)
#pragma unroll
            for (int nt = 0; nt < 4; ++nt)
#pragma unroll
                for (int r = 0; r < 4; ++r) {
                    int rl = wm + mt * 16 + g + ((r >> 1) << 3);
                    int cl = wn + nt * 8 + 2 * tg + (r & 1);
                    int row = bm + rl, col = bn + cl;
                    if (row < M && col < N) {
                        float v = acc[mt][nt][r] + red[rl][cl];
                        if (bias) v += bias[col];
                        if (Ch) Ch[(size_t)row * ldc + col] = __float2half_rn(v);
                        else    C [(size_t)row * ldc + col] = v;
                    }
                }
    }
}

// ---------------- 4-stage cp.async split-K gates GEMM + fused LSTM ----------------
__global__ __launch_bounds__(256)
void gemm_gates_sk(const __half* __restrict__ A, const __half* __restrict__ B,
                   const float* __restrict__ bg, const float* __restrict__ Y,
                   const float* __restrict__ WohT, const int* __restrict__ text, int s,
                   float* __restrict__ c, __half* __restrict__ h_h,
                   __half* __restrict__ outh_h)
{
    extern __shared__ __align__(16) char sraw[];
    __half (*As)[64][SMP] = reinterpret_cast<__half(*)[64][SMP]>(sraw);
    __half (*Bs)[64][SMP] = reinterpret_cast<__half(*)[64][SMP]>(sraw + NST * STG_BYTES);

    const int tid  = threadIdx.x;
    const int bm   = blockIdx.x * 64;
    const int bn   = blockIdx.y * 64;
    const int w    = tid >> 5, lane = tid & 31;
    const int g    = lane >> 2, tg = lane & 3;
    const int kg   = w >> 2;
    const int ws   = w & 3;
    const int wm   = (ws & 1) * 32;
    const int wn   = (ws >> 1) * 32;
    const int ks   = kg << 4;

    float acc[2][4][4];
#pragma unroll
    for (int mt = 0; mt < 2; ++mt)
#pragma unroll
        for (int nt = 0; nt < 4; ++nt)
#pragma unroll
            for (int r = 0; r < 4; ++r) acc[mt][nt][r] = 0.f;

    const int nk = II >> 5;
    const int lr = tid >> 2, lc = (tid & 3) * 8;
    const __half* aptr = A + (size_t)(bm + lr) * II + lc;
    const __half* bptr = B + (size_t)(bn + lr) * II + lc;
    const uint32_t adst0 = (uint32_t)__cvta_generic_to_shared(&As[0][lr][lc]);
    const uint32_t bdst0 = (uint32_t)__cvta_generic_to_shared(&Bs[0][lr][lc]);

#pragma unroll
    for (int p = 0; p < NST - 1; ++p) {
        cp_async16(adst0 + p * STG_BYTES, aptr + p * 32, 16);
        cp_async16(bdst0 + p * STG_BYTES, bptr + p * 32, 16);
        cp_commit();
    }

    for (int kt = 0; kt < nk; ++kt) {
        cp_wait(kt, nk);
        __syncthreads();

        if (kt + NST - 1 < nk) {
            int st = (kt + NST - 1) % NST;
            cp_async16(adst0 + st * STG_BYTES, aptr + (kt + NST - 1) * 32, 16);
            cp_async16(bdst0 + st * STG_BYTES, bptr + (kt + NST - 1) * 32, 16);
            cp_commit();
        }

        const int buf = kt % NST;
        unsigned a[2][4];
#pragma unroll
        for (int mt = 0; mt < 2; ++mt) {
            int r0 = wm + mt * 16 + g;
            a[mt][0] = *reinterpret_cast<const unsigned*>(&As[buf][r0][ks + 2 * tg]);
            a[mt][1] = *reinterpret_cast<const unsigned*>(&As[buf][r0 + 8][ks + 2 * tg]);
            a[mt][2] = *reinterpret_cast<const unsigned*>(&As[buf][r0][ks + 8 + 2 * tg]);
            a[mt][3] = *reinterpret_cast<const unsigned*>(&As[buf][r0 + 8][ks + 8 + 2 * tg]);
        }
        unsigned bf[4][2];
#pragma unroll
        for (int nt = 0; nt < 4; ++nt) {
            int n0 = wn + nt * 8 + g;
            bf[nt][0] = *reinterpret_cast<const unsigned*>(&Bs[buf][n0][ks + 2 * tg]);
            bf[nt][1] = *reinterpret_cast<const unsigned*>(&Bs[buf][n0][ks + 8 + 2 * tg]);
        }
#pragma unroll
        for (int mt = 0; mt < 2; ++mt)
#pragma unroll
            for (int nt = 0; nt < 4; ++nt)
                MMA_F16(acc[mt][nt], a[mt], bf[nt]);
    }

    // gates staging buffer aliases the As stage region
    __syncthreads();
    float (*gsm)[68] = reinterpret_cast<float(*)[68]>(sraw);

    if (kg == 1) {
#pragma unroll
        for (int mt = 0; mt < 2; ++mt)
#pragma unroll
            for (int nt = 0; nt < 4; ++nt)
#pragma unroll
                for (int r = 0; r < 4; ++r) {
                    int rl = wm + mt * 16 + g + ((r >> 1) << 3);
                    int cl = wn + nt * 8 + 2 * tg + (r & 1);
                    gsm[rl][cl] = acc[mt][nt][r];
                }
    }
    __syncthreads();
    if (kg == 0) {
#pragma unroll
        for (int mt = 0; mt < 2; ++mt)
#pragma unroll
            for (int nt = 0; nt < 4; ++nt)
#pragma unroll
                for (int r = 0; r < 4; ++r) {
                    int rl = wm + mt * 16 + g + ((r >> 1) << 3);
                    int cl = wn + nt * 8 + 2 * tg + (r & 1);
                    gsm[rl][cl] += acc[mt][nt][r];
                }
    }
    __syncthreads();

    // fused LSTM: 256 threads x 4 (row, unit) items; fast transcendentals
    {
        const int r  = tid >> 2;            // local row 0..63
        const int u0 = tid & 3;
        const int b  = bm + r;
        const int cls = text[b * SS + s];
        const float4* wo4 = reinterpret_cast<const float4*>(WohT + (size_t)cls * G4H + bn);
        const float4* bg4 = reinterpret_cast<const float4*>(bg + bn);
        const float4* Y4  = reinterpret_cast<const float4*>(Y + (size_t)b * NCOMB + HH + bn);
#pragma unroll
        for (int j = 0; j < 4; ++j) {
            int u = 4 * j + u0;             // 0..15
            float4 gv = *reinterpret_cast<const float4*>(&gsm[r][4 * u]);
            float4 bv = bg4[u];
            float4 yv = Y4[u];
            float4 wv = wo4[u];
            float gi = gv.x + bv.x + yv.x + wv.x;
            float gf = gv.y + bv.y + yv.y + wv.y;
            float gg = gv.z + bv.z + yv.z + wv.z;
            float go = gv.w + bv.w + yv.w + wv.w;

            int ug = (bn >> 2) + u;
            int cidx = b * HH + ug;
            float ci = c[cidx];
            float c2 = fsig(gf) * ci + fsig(gi) * ftanh(gg);
            float h2 = fsig(go) * ftanh(c2);

            c[cidx] = c2;
            __half h2h = __float2half_rn(h2);
            h_h[cidx] = h2h;
            outh_h[((size_t)b * SS + s) * HH + ug] = h2h;
        }
    }
}

// ---------------- fp16 GEMM, 128x128 tile, 256 threads (feat) ----------------
#define SMPB 40

__global__ __launch_bounds__(256)
void gemm_f16_big(const __half* __restrict__ A, const __half* __restrict__ B,
                  float* __restrict__ C, __half* __restrict__ Ch,
                  int M, int N, int K, int ldc)
{
    __shared__ __half As[2][128][SMPB];
    __shared__ __half Bs[2][128][SMPB];

    const int tid  = threadIdx.x;
    const int bm   = blockIdx.x * 128;
    const int bn   = blockIdx.y * 128;
    const int w    = tid >> 5, lane = tid & 31;
    const int g    = lane >> 2, tg = lane & 3;
    const int wm   = (w & 1) * 64;
    const int wn   = (w >> 1) * 32;

    float acc[4][4][4];
#pragma unroll
    for (int mt = 0; mt < 4; ++mt)
#pragma unroll
        for (int nt = 0; nt < 4; ++nt)
#pragma unroll
            for (int r = 0; r < 4; ++r) acc[mt][nt][r] = 0.f;

    uint4 stA[2], stB[2];
    const uint4 z4 = make_uint4(0u, 0u, 0u, 0u);
    const int nk = K >> 5;
    const int kld = K >> 3;

    auto ldg = [&](int k0) {
#pragma unroll
        for (int i = 0; i < 2; ++i) {
            int id = tid + i * 256;
            int r = id >> 2, cg = id & 3;
            const uint4* Ar = reinterpret_cast<const uint4*>(A) + (size_t)(bm + r) * kld + (k0 >> 3) + cg;
            const uint4* Br = reinterpret_cast<const uint4*>(B) + (size_t)(bn + r) * kld + (k0 >> 3) + cg;
            stA[i] = (bm + r < M) ? *Ar : z4;
            stB[i] = (bn + r < N) ? *Br : z4;
        }
    };
    auto sts = [&](int buf) {
#pragma unroll
        for (int i = 0; i < 2; ++i) {
            int id = tid + i * 256;
            int r = id >> 2, cg = id & 3;
            *reinterpret_cast<uint4*>(&As[buf][r][cg * 8]) = stA[i];
            *reinterpret_cast<uint4*>(&Bs[buf][r][cg * 8]) = stB[i];
        }
    };

    ldg(0); sts(0);
    __syncthreads();

    for (int kt = 0; kt < nk; ++kt) {
        const int buf = kt & 1;
        if (kt + 1 < nk) ldg((kt + 1) << 5);

#pragma unroll
        for (int ks = 0; ks < 32; ks += 16) {
            unsigned a[4][4];
#pragma unroll
            for (int mt = 0; mt < 4; ++mt) {
                int r0 = wm + mt * 16 + g;
                a[mt][0] = *reinterpret_cast<const unsigned*>(&As[buf][r0][ks + 2 * tg]);
                a[mt][1] = *reinterpret_cast<const unsigned*>(&As[buf][r0 + 8][ks + 2 * tg]);
                a[mt][2] = *reinterpret_cast<const unsigned*>(&As[buf][r0][ks + 8 + 2 * tg]);
                a[mt][3] = *reinterpret_cast<const unsigned*>(&As[buf][r0 + 8][ks + 8 + 2 * tg]);
            }
            unsigned bf[4][2];
#pragma unroll
            for (int nt = 0; nt < 4; ++nt) {
                int n0 = wn + nt * 8 + g;
                bf[nt][0] = *reinterpret_cast<const unsigned*>(&Bs[buf][n0][ks + 2 * tg]);
                bf[nt][1] = *reinterpret_cast<const unsigned*>(&Bs[buf][n0][ks + 8 + 2 * tg]);
            }
#pragma unroll
            for (int mt = 0; mt < 4; ++mt)
#pragma unroll
                for (int nt = 0; nt < 4; ++nt)
                    MMA_F16(acc[mt][nt], a[mt], bf[nt]);
        }

        if (kt + 1 < nk) { __syncthreads(); sts((kt + 1) & 1); }
        __syncthreads();
    }

#pragma unroll
    for (int mt = 0; mt < 4; ++mt)
#pragma unroll
        for (int nt = 0; nt < 4; ++nt)
#pragma unroll
            for (int r = 0; r < 4; ++r) {
                int row = bm + wm + mt * 16 + g + ((r >> 1) << 3);
                int col = bn + wn + nt * 8 + 2 * tg + (r & 1);
                if (row < M && col < N) {
                    float v = acc[mt][nt][r];
                    if (Ch) Ch[(size_t)row * ldc + col] = __float2half_rn(v);
                    else    C [(size_t)row * ldc + col] = v;
                }
            }
}

// ---------------- fused attention (fp16, uint4 loads) ----------------
__global__ __launch_bounds__(256)
void att_kernel(const uint4* __restrict__ H4, const uint4* __restrict__ F4,
                const float* __restrict__ hp, int hp_ld,
                const float* __restrict__ w_score, __half2* __restrict__ ctx)
{
    __shared__ float e_sh[TT];
    __shared__ float red_sh[2];
    __shared__ float red4[4][64][8];

    const int b = blockIdx.x;
    const int tid = threadIdx.x;
    const int warp = tid >> 5, lane = tid & 31;

    float2 hpv[8], wsv[8];
    {
        const float2* hp2 = reinterpret_cast<const float2*>(hp + (size_t)b * hp_ld);
        const float2* ws2 = reinterpret_cast<const float2*>(w_score);
#pragma unroll
        for (int j = 0; j < 2; ++j)
#pragma unroll
            for (int q = 0; q < 4; ++q) {
                int idx = 4 * (j * 32 + lane) + q;
                hpv[j * 4 + q] = hp2[idx];
                wsv[j * 4 + q] = ws2[idx];
            }
    }

    for (int t0 = warp; t0 < TT; t0 += 16) {
        const int t1 = t0 + 8;
        const uint4* f0 = F4 + ((size_t)b * TT + t0) * 64;
        const uint4* f1 = F4 + ((size_t)b * TT + t1) * 64;
        uint4 u0a = f0[lane], u0b = f0[32 + lane];
        uint4 u1a = f1[lane], u1b = f1[32 + lane];
        float acc0 = 0.f, acc1 = 0.f;
#pragma unroll
        for (int q = 0; q < 4; ++q) {
            {
                float2 f = __half22float2(reinterpret_cast<const __half2*>(&u0a)[q]);
                float2 hv = hpv[q], wv = wsv[q];
                float a0, a1;
                asm("tanh.approx.f32 %0, %1;" : "=f"(a0) : "f"(f.x + hv.x));
                asm("tanh.approx.f32 %0, %1;" : "=f"(a1) : "f"(f.y + hv.y));
                acc0 = fmaf(a0, wv.x, fmaf(a1, wv.y, acc0));
            }
            {
                float2 f = __half22float2(reinterpret_cast<const __half2*>(&u0b)[q]);
                float2 hv = hpv[4 + q], wv = wsv[4 + q];
                float a0, a1;
                asm("tanh.approx.f32 %0, %1;" : "=f"(a0) : "f"(f.x + hv.x));
                asm("tanh.approx.f32 %0, %1;" : "=f"(a1) : "f"(f.y + hv.y));
                acc0 = fmaf(a0, wv.x, fmaf(a1, wv.y, acc0));
            }
            {
                float2 f = __half22float2(reinterpret_cast<const __half2*>(&u1a)[q]);
                float2 hv = hpv[q], wv = wsv[q];
                float a0, a1;
                asm("tanh.approx.f32 %0, %1;" : "=f"(a0) : "f"(f.x + hv.x));
                asm("tanh.approx.f32 %0, %1;" : "=f"(a1) : "f"(f.y + hv.y));
                acc1 = fmaf(a0, wv.x, fmaf(a1, wv.y, acc1));
            }
            {
                float2 f = __half22float2(reinterpret_cast<const __half2*>(&u1b)[q]);
                float2 hv = hpv[4 + q], wv = wsv[4 + q];
                float a0, a1;
                asm("tanh.approx.f32 %0, %1;" : "=f"(a0) : "f"(f.x + hv.x));
                asm("tanh.approx.f32 %0, %1;" : "=f"(a1) : "f"(f.y + hv.y));
                acc1 = fmaf(a0, wv.x, fmaf(a1, wv.y, acc1));
            }
        }
#pragma unroll
        for (int o = 16; o > 0; o >>= 1) {
            acc0 += __shfl_xor_sync(0xffffffffu, acc0, o);
            acc1 += __shfl_xor_sync(0xffffffffu, acc1, o);
        }
        if (lane == 0) { e_sh[t0] = acc0; e_sh[t1] = acc1; }
    }
    __syncthreads();

    if (tid < 32) {
        float m = fmaxf(fmaxf(e_sh[tid], e_sh[tid + 32]),
                        fmaxf(e_sh[tid + 64], e_sh[tid + 96]));
#pragma unroll
        for (int o = 16; o > 0; o >>= 1) m = fmaxf(m, __shfl_xor_sync(0xffffffffu, m, o));
        if (tid == 0) red_sh[0] = m;
    }
    __syncthreads();
    const float mx = red_sh[0];
    if (tid < TT) e_sh[tid] = __expf(e_sh[tid] - mx);
    __syncthreads();
    if (tid < 32) {
        float ssum = e_sh[tid] + e_sh[tid + 32] + e_sh[tid + 64] + e_sh[tid + 96];
#pragma unroll
        for (int o = 16; o > 0; o >>= 1) ssum += __shfl_xor_sync(0xffffffffu, ssum, o);
        if (tid == 0) red_sh[1] = 1.f / ssum;
    }
    __syncthreads();

    {
        const int tg4 = tid >> 6, ti = tid & 63;
        const uint4* Hb = H4 + (size_t)b * TT * 64 + ti;
        float acc[8];
#pragma unroll
        for (int q = 0; q < 8; ++q) acc[q] = 0.f;
        const int tbeg = tg4 * 32;
#pragma unroll 4
        for (int t = tbeg; t < tbeg + 32; ++t) {
            uint4 u = Hb[(size_t)t * 64];
            float a = e_sh[t];
#pragma unroll
            for (int q = 0; q < 4; ++q) {
                float2 v = __half22float2(reinterpret_cast<const __half2*>(&u)[q]);
                acc[2 * q]     = fmaf(a, v.x, acc[2 * q]);
                acc[2 * q + 1] = fmaf(a, v.y, acc[2 * q + 1]);
            }
        }
#pragma unroll
        for (int q = 0; q < 8; ++q) red4[tg4][ti][q] = acc[q];
    }
    __syncthreads();

    if (tid < 64) {
        const float inv = red_sh[1];
        __half2 o4[4];
#pragma unroll
        for (int q = 0; q < 4; ++q) {
            float x = (red4[0][tid][2*q]   + red4[1][tid][2*q] +
                       red4[2][tid][2*q]   + red4[3][tid][2*q]) * inv;
            float y = (red4[0][tid][2*q+1] + red4[1][tid][2*q+1] +
                       red4[2][tid][2*q+1] + red4[3][tid][2*q+1]) * inv;
            o4[q] = __float22half2_rn(make_float2(x, y));
        }
        *reinterpret_cast<uint4*>(&ctx[(size_t)b * (II / 2) + tid * 4]) =
            *reinterpret_cast<const uint4*>(o4);
    }
}

// ---------------- host launcher ----------------
extern "C" void kernel_launch(void* const* d_in, const int* in_sizes, int n_in,
                              void* d_out, int out_size)
{
    const float* batch_H = (const float*)d_in[0];
    const int*   text    = (const int*)  d_in[1];
    const float* W_feat  = (const float*)d_in[2];
    const float* W_hid   = (const float*)d_in[3];
    const float* b_hid   = (const float*)d_in[4];
    const float* w_score = (const float*)d_in[5];
    const float* W_ih    = (const float*)d_in[6];
    const float* W_hh    = (const float*)d_in[7];
    const float* b_ih    = (const float*)d_in[8];
    const float* b_hh    = (const float*)d_in[9];
    const float* W_gen   = (const float*)d_in[10];
    const float* b_gen   = (const float*)d_in[11];
    float* out = (float*)d_out;

    float *c, *Y, *WohT, *bg, *bcomb;
    __half2 *feat_h, *H_h, *ctx_h;
    __half *h_h, *outh_h, *Wx_h, *Wcomb_h, *Wfeat_h, *Wgen_h;
    cudaGetSymbolAddress((void**)&feat_h,  g_feat_h);
    cudaGetSymbolAddress((void**)&H_h,     g_H_h);
    cudaGetSymbolAddress((void**)&h_h,     g_h_h);
    cudaGetSymbolAddress((void**)&c,       g_c);
    cudaGetSymbolAddress((void**)&Y,       g_Y);
    cudaGetSymbolAddress((void**)&ctx_h,   g_ctx_h);
    cudaGetSymbolAddress((void**)&outh_h,  g_outh_h);
    cudaGetSymbolAddress((void**)&Wx_h,    g_Wx_h);
    cudaGetSymbolAddress((void**)&Wcomb_h, g_Wcomb_h);
    cudaGetSymbolAddress((void**)&Wfeat_h, g_Wfeat_h);
    cudaGetSymbolAddress((void**)&Wgen_h,  g_Wgen_h);
    cudaGetSymbolAddress((void**)&bcomb,   g_bcomb);
    cudaGetSymbolAddress((void**)&WohT,    g_WohT);
    cudaGetSymbolAddress((void**)&bg,      g_bg);

    // opt-in to 57 KB dynamic smem for the pipelined GEMMs (idempotent)
    cudaFuncSetAttribute(gemm_f16_sk,
                         cudaFuncAttributeMaxDynamicSharedMemorySize, SMEM_SK);
    cudaFuncSetAttribute(gemm_gates_sk,
                         cudaFuncAttributeMaxDynamicSharedMemorySize, SMEM_SK);

    // pack weights (fp16, gate-interleaved) + fp16 batch_H + zero state
    pack_kernel<<<512, 256>>>(W_ih, b_ih, b_hh, W_hid, W_hh, b_hid,
                              W_feat, W_gen, batch_H);

    // feat[BT, H] = batch_H @ W_feat^T  -> fp16
    gemm_f16_big<<<dim3((BB * TT) / 128, HH / 128), 256>>>(
        (const __half*)H_h, Wfeat_h, nullptr, (__half*)feat_h,
        BB * TT, HH, II, HH);

    for (int s = 0; s < SS; ++s) {
        // Y = h @ [W_hid ; W_hh_il]^T + [b_hid ; 0]   -> [B, 2560] fp32
        gemm_f16_sk<<<dim3(BB / 64, NCOMB / 64), 256, SMEM_SK>>>(
            h_h, Wcomb_h, bcomb, Y, nullptr, BB, NCOMB, HH, NCOMB);

        // fused attention (hp = Y[:, :512]) -> fp16 ctx
        att_kernel<<<BB, 256>>>((const uint4*)H_h, (const uint4*)feat_h,
                                Y, NCOMB, w_score, ctx_h);

        // gates GEMM + fused LSTM cell
        gemm_gates_sk<<<dim3(BB / 64, G4H / 64), 256, SMEM_SK>>>(
            (const __half*)ctx_h, Wx_h, bg, Y, WohT, text, s, c, h_h, outh_h);
    }

    // probs[B*S, C] = outh @ W_gen^T + b_gen
    gemm_f16_sk<<<dim3((BB * SS) / 64, (CC + 63) / 64), 256, SMEM_SK>>>(
        outh_h, Wgen_h, b_gen, out, nullptr, BB * SS, CC, HH, CC);
}